// round 3
// baseline (speedup 1.0000x reference)
#include <cuda_runtime.h>
#include <math.h>

typedef unsigned long long ull;

#define BATCH 512
#define CIN   64
#define LIN   1024
#define COUTC 256
#define K1    32
#define STR1  16
#define TT    63
#define NCLS  2
#define KTOT  2048   // CIN*K1

#define ZROWS 66     // dup-z rows: t = -1 .. 64  (row = t+1), each row 512 floats (dup)
#define BSTR  66     // bufA / d1 row stride

// ---------------- device scratch ----------------
__device__ float g_z1[BATCH * TT * COUTC];       // [n][t][co]
__device__ float g_c2wt[COUTC * 3 * COUTC];      // [(ci*3+k)][2*cog+half]  (co pairs interleaved)
__device__ float g_d1wt[COUTC * COUTC];          // [c][o]
__device__ float g_bn2a[COUTC];

// ---------------- packed fp32x2 helpers ----------------
__device__ __forceinline__ ull pk2(float lo, float hi) {
    ull r; asm("mov.b64 %0, {%1,%2};" : "=l"(r) : "f"(lo), "f"(hi)); return r;
}
__device__ __forceinline__ ull fma2(ull a, ull b, ull c) {
    ull d; asm("fma.rn.f32x2 %0, %1, %2, %3;" : "=l"(d) : "l"(a), "l"(b), "l"(c)); return d;
}
__device__ __forceinline__ float2 upk2(ull v) {
    float2 f; asm("mov.b64 {%0,%1}, %2;" : "=f"(f.x), "=f"(f.y) : "l"(v)); return f;
}

// ---------------- conv1 (im2col GEMM, M=32256 K=2048 N=256) + BN1 ----------------
// Self-contained: reads conv weights in original [co][ci][k] layout, BN scale inline.
__global__ __launch_bounds__(256, 2)
void conv1_gemm(const float* __restrict__ x,
                const float* __restrict__ c1w,
                const float* __restrict__ c1b,
                const float* __restrict__ bn1g,
                const float* __restrict__ bn1b,
                const float* __restrict__ bn1m,
                const float* __restrict__ bn1v)
{
    __shared__ __align__(16) float As2[2][16][256];   // duplicated A pairs
    __shared__ __align__(16) float Bs[2][16][128];
    const int tid = threadIdx.x;
    const int mBase = blockIdx.x * 128;
    const int nBase = blockIdx.y * 128;

    // ---- A loader geometry (same as before) ----
    const int q0  = tid * 2;
    const int r0  = q0 >> 2;               // A row 0..127
    const int c40 = (q0 & 3) * 4;          // 0 or 8
    const int m0 = mBase + r0;
    const int n_idx = m0 / TT;
    const int t_idx = m0 - n_idx * TT;
    const float* xrow = x + ((size_t)n_idx * CIN) * LIN + t_idx * STR1;

    // ---- B loader geometry: direct from c1w [co][ci][k] ----
    const int coB   = tid & 127;           // col within tile
    const int khalf = (tid >> 7) * 8;      // 0 or 8
    const float* wrow = c1w + (size_t)(nBase + coB) * KTOT;  // flattened (ci,k) contiguous

    const int tm = (tid >> 4) * 8;
    const int tn = (tid & 15) * 8;

    ull acc[8][4];
    #pragma unroll
    for (int i = 0; i < 8; i++)
        #pragma unroll
        for (int j = 0; j < 4; j++) acc[i][j] = 0ULL;

    float4 apf0, apf1, bpf0, bpf1;

    #define LOAD_REGS(KB) {                                                   \
        int col = (KB) + c40;                                                 \
        apf0 = *(const float4*)(xrow + (size_t)(col >> 5) * LIN + (col & 31));\
        col += 4;                                                             \
        apf1 = *(const float4*)(xrow + (size_t)(col >> 5) * LIN + (col & 31));\
        bpf0 = *(const float4*)(wrow + (KB) + khalf);                         \
        bpf1 = *(const float4*)(wrow + (KB) + khalf + 4);                     \
    }
    #define STORE_SMEM(B) {                                                   \
        *(ull*)&As2[B][c40 + 0][2 * r0] = pk2(apf0.x, apf0.x);                \
        *(ull*)&As2[B][c40 + 1][2 * r0] = pk2(apf0.y, apf0.y);                \
        *(ull*)&As2[B][c40 + 2][2 * r0] = pk2(apf0.z, apf0.z);                \
        *(ull*)&As2[B][c40 + 3][2 * r0] = pk2(apf0.w, apf0.w);                \
        *(ull*)&As2[B][c40 + 4][2 * r0] = pk2(apf1.x, apf1.x);                \
        *(ull*)&As2[B][c40 + 5][2 * r0] = pk2(apf1.y, apf1.y);                \
        *(ull*)&As2[B][c40 + 6][2 * r0] = pk2(apf1.z, apf1.z);                \
        *(ull*)&As2[B][c40 + 7][2 * r0] = pk2(apf1.w, apf1.w);                \
        Bs[B][khalf + 0][coB] = bpf0.x; Bs[B][khalf + 1][coB] = bpf0.y;       \
        Bs[B][khalf + 2][coB] = bpf0.z; Bs[B][khalf + 3][coB] = bpf0.w;       \
        Bs[B][khalf + 4][coB] = bpf1.x; Bs[B][khalf + 5][coB] = bpf1.y;       \
        Bs[B][khalf + 6][coB] = bpf1.z; Bs[B][khalf + 7][coB] = bpf1.w;       \
    }

    LOAD_REGS(0);
    STORE_SMEM(0);
    __syncthreads();

    int buf = 0;
    for (int kb = 0; kb < KTOT; kb += 16) {
        const bool more = (kb + 16) < KTOT;
        if (more) LOAD_REGS(kb + 16);

        const float (*A)[256] = As2[buf];
        const float (*B)[128] = Bs[buf];
        #pragma unroll
        for (int kk = 0; kk < 16; kk++) {
            ulonglong2 av0 = *(const ulonglong2*)&A[kk][2 * tm];
            ulonglong2 av1 = *(const ulonglong2*)&A[kk][2 * tm + 4];
            ulonglong2 av2 = *(const ulonglong2*)&A[kk][2 * tm + 8];
            ulonglong2 av3 = *(const ulonglong2*)&A[kk][2 * tm + 12];
            ulonglong2 p0 = *(const ulonglong2*)&B[kk][tn];
            ulonglong2 p1 = *(const ulonglong2*)&B[kk][tn + 4];
            ull b0 = p0.x, b1 = p0.y, b2 = p1.x, b3 = p1.y;
            #define FMA_ROW(I, AP)                        \
                acc[I][0] = fma2(AP, b0, acc[I][0]);      \
                acc[I][1] = fma2(AP, b1, acc[I][1]);      \
                acc[I][2] = fma2(AP, b2, acc[I][2]);      \
                acc[I][3] = fma2(AP, b3, acc[I][3]);
            FMA_ROW(0, av0.x) FMA_ROW(1, av0.y) FMA_ROW(2, av1.x) FMA_ROW(3, av1.y)
            FMA_ROW(4, av2.x) FMA_ROW(5, av2.y) FMA_ROW(6, av3.x) FMA_ROW(7, av3.y)
            #undef FMA_ROW
        }
        if (more) STORE_SMEM(buf ^ 1);
        __syncthreads();
        buf ^= 1;
    }
    #undef LOAD_REGS
    #undef STORE_SMEM

    // epilogue: ((conv + b) - m) * (g/sqrt(v+eps)) + beta  -> g_z1 [n][t][co]
    float sc[8], bb[8], mm[8], cb[8];
    #pragma unroll
    for (int jj = 0; jj < 8; jj++) {
        int co = nBase + tn + jj;
        sc[jj] = bn1g[co] / sqrtf(bn1v[co] + 1e-5f);
        bb[jj] = bn1b[co]; mm[jj] = bn1m[co]; cb[jj] = c1b[co];
    }
    #pragma unroll
    for (int i = 0; i < 8; i++) {
        int m = mBase + tm + i;
        float o_[8];
        #pragma unroll
        for (int j = 0; j < 4; j++) {
            float2 v = upk2(acc[i][j]);
            o_[2 * j] = v.x; o_[2 * j + 1] = v.y;
        }
        #pragma unroll
        for (int jj = 0; jj < 8; jj++) {
            float t1 = (o_[jj] + cb[jj]) - mm[jj];
            o_[jj] = fmaf(t1, sc[jj], bb[jj]);
        }
        float* dst = g_z1 + (size_t)m * COUTC + nBase + tn;
        *(float4*)dst       = make_float4(o_[0], o_[1], o_[2], o_[3]);
        *(float4*)(dst + 4) = make_float4(o_[4], o_[5], o_[6], o_[7]);
    }
}

// ---------------- prep: conv2/dense1 weight layouts + BN2 scale ----------------
__global__ void prep_kernel(const float* __restrict__ c2w,
                            const float* __restrict__ d1w,
                            const float* __restrict__ bn2g, const float* __restrict__ bn2v)
{
    int i = blockIdx.x * blockDim.x + threadIdx.x;
    if (i < COUTC * 3 * COUTC) {                  // conv2 w: pair-interleaved
        int row = i >> 8, j = i & 255;
        int ci = row / 3, k = row - 3 * ci;
        int co = (j >> 1) + 128 * (j & 1);
        g_c2wt[i] = c2w[(co * COUTC + ci) * 3 + k];
    }
    if (i < COUTC * COUTC) {                      // dense w1: [o][c] -> [c][o]
        int c = i >> 8, o = i & 255;
        g_d1wt[i] = d1w[o * COUTC + c];
    }
    if (i < COUTC) {
        g_bn2a[i] = bn2g[i] / sqrtf(bn2v[i] + 1e-5f);
    }
}

// ---------------- mega kernel ----------------
__global__ __launch_bounds__(512, 1)
void mega_kernel(const float* __restrict__ c2b,
                 const float* __restrict__ bn2b,
                 const float* __restrict__ bn2m,
                 const float* __restrict__ d2w,
                 float* __restrict__ out)
{
    extern __shared__ float sm[];
    float* zin  = sm;                          // dup-z: [row 0..65][512] ; later reused [o][BSTR]
    float* bufA = sm + ZROWS * 2 * COUTC;      // [co][BSTR]

    const int n = blockIdx.x;
    const int tid = threadIdx.x;

    // ---- load z1[n] into dup rows 1..63; zero rows 0,64,65 ----
    {
        float4* z4 = (float4*)zin;                                  // row 0: 512 floats
        for (int i = tid; i < (2 * COUTC) / 4; i += 512) z4[i] = make_float4(0, 0, 0, 0);
        float4* zp4 = (float4*)(zin + 64 * 2 * COUTC);              // rows 64,65: 1024 floats
        for (int i = tid; i < (4 * COUTC) / 4; i += 512) zp4[i] = make_float4(0, 0, 0, 0);
        const float4* src = (const float4*)(g_z1 + (size_t)n * (TT * COUTC));
        float4* dstv = (float4*)(zin + 2 * COUTC);                  // row 1 start
        for (int i = tid; i < (TT * COUTC) / 4; i += 512) {
            float4 v = src[i];
            dstv[2 * i]     = make_float4(v.x, v.x, v.y, v.y);
            dstv[2 * i + 1] = make_float4(v.z, v.z, v.w, v.w);
        }
    }
    __syncthreads();

    // ---- conv2 (k=3,p=1) + BN2 : fp32x2 lanes = (co, co+128), z via dup LDS.64 ----
    {
        const int cog = tid & 127;
        const int th  = tid >> 7;
        const int t0  = th * 16;
        ull acc[16];
        #pragma unroll
        for (int t = 0; t < 16; t++) acc[t] = 0ULL;

        const float* zb = zin + t0 * (2 * COUTC);     // row t0 => t = t0-1
        const ull* wbase = (const ull*)g_c2wt;

        for (int ci = 0; ci < COUTC; ci++) {
            ull w0 = wbase[(ci * 3 + 0) * 128 + cog];
            ull w1 = wbase[(ci * 3 + 1) * 128 + cog];
            ull w2 = wbase[(ci * 3 + 2) * 128 + cog];
            ull zz[18];
            #pragma unroll
            for (int j = 0; j < 18; j++)
                zz[j] = *(const ull*)(zb + j * (2 * COUTC) + 2 * ci);
            #pragma unroll
            for (int t = 0; t < 16; t++) {
                acc[t] = fma2(w0, zz[t],     acc[t]);
                acc[t] = fma2(w1, zz[t + 1], acc[t]);
                acc[t] = fma2(w2, zz[t + 2], acc[t]);
            }
        }
        const int coA = cog, coB = cog + 128;
        const float cbA = c2b[coA], mA = bn2m[coA], sA = g_bn2a[coA], bA = bn2b[coA];
        const float cbB = c2b[coB], mB = bn2m[coB], sB = g_bn2a[coB], bB = bn2b[coB];
        __syncthreads();   // all conv2 reads of zin done before bufA writes? (bufA disjoint; sync for clarity of z reuse later)
        #pragma unroll
        for (int t = 0; t < 16; t++) {
            float2 v = upk2(acc[t]);
            int tt = t0 + t;
            bufA[coA * BSTR + tt] = fmaf((v.x + cbA) - mA, sA, bA);
            bufA[coB * BSTR + tt] = fmaf((v.y + cbB) - mB, sB, bB);
        }
    }
    __syncthreads();

    // ---- encoder CUBA LIF: thr 0.3, cd 0.9, vd 0.9 ----
    if (tid < COUTC) {
        float* row = bufA + tid * BSTR;
        const float cd = (float)(1.0 - 0.9);
        const float vd = (float)(1.0 - 0.9);
        float cur = 0.0f, vol = 0.0f;
        #pragma unroll 1
        for (int t = 0; t < TT; t++) {
            float xv = row[t];
            cur = fmaf(cd, cur, xv);
            vol = fmaf(vd, vol, cur);
            float s = ((vol - 0.3f) >= 0.0f) ? 1.0f : 0.0f;
            row[t] = s;
            vol = vol * (1.0f - s);
        }
        row[TT] = 0.0f;
    }
    __syncthreads();

    // ---- dense1: fp32x2 lanes = t-pairs, direct LDS.64 operands; write into zin region ----
    {
        const int og = tid & 127;
        const int th = tid >> 7;
        const int t0 = th * 16;
        ull a0[8], a1[8];
        #pragma unroll
        for (int p = 0; p < 8; p++) { a0[p] = 0ULL; a1[p] = 0ULL; }

        for (int c = 0; c < COUTC; c++) {
            float wa = g_d1wt[c * COUTC + og];
            float wb = g_d1wt[c * COUTC + og + 128];
            ull wap = pk2(wa, wa), wbp = pk2(wb, wb);
            const ull* sp = (const ull*)(bufA + c * BSTR + t0);
            #pragma unroll
            for (int p = 0; p < 8; p++) {
                ull s = sp[p];
                a0[p] = fma2(wap, s, a0[p]);
                a1[p] = fma2(wbp, s, a1[p]);
            }
        }
        ull* d0 = (ull*)(zin + og * BSTR + t0);
        ull* d1 = (ull*)(zin + (og + 128) * BSTR + t0);
        #pragma unroll
        for (int p = 0; p < 8; p++) { d0[p] = a0[p]; d1[p] = a1[p]; }
    }
    __syncthreads();

    // ---- dense1 CUBA LIF: thr 0.1, cd=1, vd=0.1 ----
    if (tid < COUTC) {
        float* row = zin + tid * BSTR;
        const float vdD = (float)(1.0 - 0.1);
        float vol = 0.0f;
        #pragma unroll 1
        for (int t = 0; t < TT; t++) {
            float xv = row[t];
            vol = fmaf(vdD, vol, xv);
            float s = ((vol - 0.1f) >= 0.0f) ? 1.0f : 0.0f;
            row[t] = s;
            vol = vol * (1.0f - s);
        }
    }
    __syncthreads();

    // ---- dense2: [2 x 256] ----
    if (tid < NCLS * TT) {
        int cls = tid / TT, t = tid - cls * TT;
        const float* w = d2w + cls * COUTC;
        float a = 0.0f;
        #pragma unroll 4
        for (int c = 0; c < COUTC; c++) a = fmaf(w[c], zin[c * BSTR + t], a);
        bufA[tid] = a;
    }
    __syncthreads();

    // ---- dense2 CUBA LIF + output ----
    if (tid < NCLS) {
        const float vdD = (float)(1.0 - 0.1);
        float vol = 0.0f;
        const float* rowi = bufA + tid * TT;
        float* rowo = out + (size_t)n * (NCLS * TT) + tid * TT;
        #pragma unroll 1
        for (int t = 0; t < TT; t++) {
            float xv = rowi[t];
            vol = fmaf(vdD, vol, xv);
            float s = ((vol - 0.1f) >= 0.0f) ? 1.0f : 0.0f;
            rowo[t] = s;
            vol = vol * (1.0f - s);
        }
    }
}

// ---------------- launch ----------------
extern "C" void kernel_launch(void* const* d_in, const int* in_sizes, int n_in,
                              void* d_out, int out_size)
{
    const float* x    = (const float*)d_in[0];
    const float* c1w  = (const float*)d_in[1];
    const float* c1b  = (const float*)d_in[2];
    const float* bn1g = (const float*)d_in[3];
    const float* bn1b = (const float*)d_in[4];
    const float* bn1m = (const float*)d_in[5];
    const float* bn1v = (const float*)d_in[6];
    const float* c2w  = (const float*)d_in[7];
    const float* c2b  = (const float*)d_in[8];
    const float* bn2g = (const float*)d_in[9];
    const float* bn2b = (const float*)d_in[10];
    const float* bn2m = (const float*)d_in[11];
    const float* bn2v = (const float*)d_in[12];
    const float* d1w  = (const float*)d_in[13];
    const float* d2w  = (const float*)d_in[14];
    float* out = (float*)d_out;

    const int smem_bytes = (ZROWS * 2 * COUTC + COUTC * BSTR) * (int)sizeof(float);
    cudaFuncSetAttribute(mega_kernel, cudaFuncAttributeMaxDynamicSharedMemorySize, smem_bytes);

    // conv1 first (self-contained) so the profiler's first-node capture shows it
    dim3 g1(252, 2);
    conv1_gemm<<<g1, 256>>>(x, c1w, c1b, bn1g, bn1b, bn1m, bn1v);

    prep_kernel<<<768, 256>>>(c2w, d1w, bn2g, bn2v);

    mega_kernel<<<BATCH, 512, smem_bytes>>>(c2b, bn2b, bn2m, d2w, out);
}

// round 4
// speedup vs baseline: 1.1822x; 1.1822x over previous
#include <cuda_runtime.h>
#include <math.h>

typedef unsigned long long ull;

#define BATCH 512
#define CIN   64
#define LIN   1024
#define COUTC 256
#define K1    32
#define STR1  16
#define TT    63
#define NCLS  2
#define KTOT  2048   // CIN*K1

#define ZROWS 66     // dup-z rows: t = -1 .. 64  (row = t+1), each row 512 floats (dup)
#define BSTR  66     // bufA / d1 row stride

// ---------------- device scratch ----------------
__device__ float g_z1[BATCH * TT * COUTC];       // [n][t][co]
__device__ float g_c2wt[COUTC * 3 * COUTC];      // [(ci*3+k)][2*cog+half]  (co pairs interleaved)
__device__ float g_d1wt[COUTC * COUTC];          // [c][o]
__device__ float g_bn2a[COUTC];

// ---------------- packed fp32x2 helpers ----------------
__device__ __forceinline__ ull pk2(float lo, float hi) {
    ull r; asm("mov.b64 %0, {%1,%2};" : "=l"(r) : "f"(lo), "f"(hi)); return r;
}
__device__ __forceinline__ ull fma2(ull a, ull b, ull c) {
    ull d; asm("fma.rn.f32x2 %0, %1, %2, %3;" : "=l"(d) : "l"(a), "l"(b), "l"(c)); return d;
}
__device__ __forceinline__ float2 upk2(ull v) {
    float2 f; asm("mov.b64 {%0,%1}, %2;" : "=f"(f.x), "=f"(f.y) : "l"(v)); return f;
}

// ---------------- conv1 (im2col GEMM, M=32256 K=2048 N=256) + BN1 ----------------
// Tile 256(M) x 64(N) x 16(K). Warp = one 8-wide N group (B reads broadcast),
// lane = one 8-row M group (A reads conflict-free LDS.128, no duplication).
__global__ __launch_bounds__(256, 2)
void conv1_gemm(const float* __restrict__ x,
                const float* __restrict__ c1w,
                const float* __restrict__ c1b,
                const float* __restrict__ bn1g,
                const float* __restrict__ bn1b,
                const float* __restrict__ bn1m,
                const float* __restrict__ bn1v)
{
    __shared__ __align__(16) float As[2][16][256];
    __shared__ __align__(16) float Bs[2][16][64];
    const int tid  = threadIdx.x;
    const int lane = tid & 31;
    const int w    = tid >> 5;              // warp 0..7 -> n-group
    const int mBase = blockIdx.x * 256;
    const int nBase = blockIdx.y * 64;

    // ---- A loader: thread tid loads im2col row (mBase+tid), 16 k per stage ----
    const int m_row = mBase + tid;
    const int n_idx = m_row / TT;
    const int t_idx = m_row - n_idx * TT;
    const float* xrow = x + ((size_t)n_idx * CIN) * LIN + t_idx * STR1;

    // ---- B loader: colocal = tid>>2 (0..63), kq = (tid&3)*4 ----
    const int colocal = tid >> 2;
    const int kq      = (tid & 3) * 4;
    const float* wrow = c1w + (size_t)(nBase + colocal) * KTOT;

    ull acc[8][4];
    #pragma unroll
    for (int i = 0; i < 8; i++)
        #pragma unroll
        for (int j = 0; j < 4; j++) acc[i][j] = 0ULL;

    float4 ap0, ap1, ap2, ap3, bpf;

    #define LOAD_REGS(KB) {                                          \
        const float* abase = xrow + (size_t)((KB) >> 5) * LIN + ((KB) & 31); \
        ap0 = *(const float4*)(abase);                               \
        ap1 = *(const float4*)(abase + 4);                           \
        ap2 = *(const float4*)(abase + 8);                           \
        ap3 = *(const float4*)(abase + 12);                          \
        bpf = *(const float4*)(wrow + (KB) + kq);                    \
    }
    #define STORE_SMEM(B) {                                          \
        As[B][0][tid]  = ap0.x; As[B][1][tid]  = ap0.y;              \
        As[B][2][tid]  = ap0.z; As[B][3][tid]  = ap0.w;              \
        As[B][4][tid]  = ap1.x; As[B][5][tid]  = ap1.y;              \
        As[B][6][tid]  = ap1.z; As[B][7][tid]  = ap1.w;              \
        As[B][8][tid]  = ap2.x; As[B][9][tid]  = ap2.y;              \
        As[B][10][tid] = ap2.z; As[B][11][tid] = ap2.w;              \
        As[B][12][tid] = ap3.x; As[B][13][tid] = ap3.y;              \
        As[B][14][tid] = ap3.z; As[B][15][tid] = ap3.w;              \
        Bs[B][kq + 0][colocal] = bpf.x; Bs[B][kq + 1][colocal] = bpf.y; \
        Bs[B][kq + 2][colocal] = bpf.z; Bs[B][kq + 3][colocal] = bpf.w; \
    }

    LOAD_REGS(0);
    STORE_SMEM(0);
    __syncthreads();

    int buf = 0;
    for (int kb = 0; kb < KTOT; kb += 16) {
        const bool more = (kb + 16) < KTOT;
        if (more) LOAD_REGS(kb + 16);

        const float (*A)[256] = As[buf];
        const float (*B)[64]  = Bs[buf];
        #pragma unroll
        for (int kk = 0; kk < 16; kk++) {
            float4 x0 = *(const float4*)&A[kk][lane * 8];
            float4 x1 = *(const float4*)&A[kk][lane * 8 + 4];
            ulonglong2 q0 = *(const ulonglong2*)&B[kk][w * 8];      // broadcast
            ulonglong2 q1 = *(const ulonglong2*)&B[kk][w * 8 + 4];  // broadcast
            ull b0 = q0.x, b1 = q0.y, b2 = q1.x, b3 = q1.y;
            ull ap;
            #define FMA_ROW(I, AV)                        \
                ap = pk2(AV, AV);                         \
                acc[I][0] = fma2(ap, b0, acc[I][0]);      \
                acc[I][1] = fma2(ap, b1, acc[I][1]);      \
                acc[I][2] = fma2(ap, b2, acc[I][2]);      \
                acc[I][3] = fma2(ap, b3, acc[I][3]);
            FMA_ROW(0, x0.x) FMA_ROW(1, x0.y) FMA_ROW(2, x0.z) FMA_ROW(3, x0.w)
            FMA_ROW(4, x1.x) FMA_ROW(5, x1.y) FMA_ROW(6, x1.z) FMA_ROW(7, x1.w)
            #undef FMA_ROW
        }
        if (more) STORE_SMEM(buf ^ 1);
        __syncthreads();
        buf ^= 1;
    }
    #undef LOAD_REGS
    #undef STORE_SMEM

    // epilogue: ((conv + b) - m) * (g/sqrt(v+eps)) + beta  -> g_z1 [n][t][co]
    float sc[8], bb[8], mm[8], cb[8];
    #pragma unroll
    for (int jj = 0; jj < 8; jj++) {
        int co = nBase + w * 8 + jj;
        sc[jj] = bn1g[co] / sqrtf(bn1v[co] + 1e-5f);
        bb[jj] = bn1b[co]; mm[jj] = bn1m[co]; cb[jj] = c1b[co];
    }
    #pragma unroll
    for (int i = 0; i < 8; i++) {
        int m = mBase + lane * 8 + i;
        float o_[8];
        #pragma unroll
        for (int j = 0; j < 4; j++) {
            float2 v = upk2(acc[i][j]);
            o_[2 * j] = v.x; o_[2 * j + 1] = v.y;
        }
        #pragma unroll
        for (int jj = 0; jj < 8; jj++) {
            float t1 = (o_[jj] + cb[jj]) - mm[jj];
            o_[jj] = fmaf(t1, sc[jj], bb[jj]);
        }
        float* dst = g_z1 + (size_t)m * COUTC + nBase + w * 8;
        *(float4*)dst       = make_float4(o_[0], o_[1], o_[2], o_[3]);
        *(float4*)(dst + 4) = make_float4(o_[4], o_[5], o_[6], o_[7]);
    }
}

// ---------------- prep: conv2/dense1 weight layouts + BN2 scale ----------------
__global__ void prep_kernel(const float* __restrict__ c2w,
                            const float* __restrict__ d1w,
                            const float* __restrict__ bn2g, const float* __restrict__ bn2v)
{
    int i = blockIdx.x * blockDim.x + threadIdx.x;
    if (i < COUTC * 3 * COUTC) {                  // conv2 w: pair-interleaved
        int row = i >> 8, j = i & 255;
        int ci = row / 3, k = row - 3 * ci;
        int co = (j >> 1) + 128 * (j & 1);
        g_c2wt[i] = c2w[(co * COUTC + ci) * 3 + k];
    }
    if (i < COUTC * COUTC) {                      // dense w1: [o][c] -> [c][o]
        int c = i >> 8, o = i & 255;
        g_d1wt[i] = d1w[o * COUTC + c];
    }
    if (i < COUTC) {
        g_bn2a[i] = bn2g[i] / sqrtf(bn2v[i] + 1e-5f);
    }
}

// ---------------- mega kernel ----------------
__global__ __launch_bounds__(512, 1)
void mega_kernel(const float* __restrict__ c2b,
                 const float* __restrict__ bn2b,
                 const float* __restrict__ bn2m,
                 const float* __restrict__ d2w,
                 float* __restrict__ out)
{
    extern __shared__ float sm[];
    float* zin  = sm;                          // dup-z: [row 0..65][512] ; later reused [o][BSTR]
    float* bufA = sm + ZROWS * 2 * COUTC;      // [co][BSTR]

    const int n = blockIdx.x;
    const int tid = threadIdx.x;

    // ---- load z1[n] into dup rows 1..63; zero rows 0,64,65 ----
    {
        float4* z4 = (float4*)zin;                                  // row 0: 512 floats
        for (int i = tid; i < (2 * COUTC) / 4; i += 512) z4[i] = make_float4(0, 0, 0, 0);
        float4* zp4 = (float4*)(zin + 64 * 2 * COUTC);              // rows 64,65: 1024 floats
        for (int i = tid; i < (4 * COUTC) / 4; i += 512) zp4[i] = make_float4(0, 0, 0, 0);
        const float4* src = (const float4*)(g_z1 + (size_t)n * (TT * COUTC));
        float4* dstv = (float4*)(zin + 2 * COUTC);                  // row 1 start
        for (int i = tid; i < (TT * COUTC) / 4; i += 512) {
            float4 v = src[i];
            dstv[2 * i]     = make_float4(v.x, v.x, v.y, v.y);
            dstv[2 * i + 1] = make_float4(v.z, v.z, v.w, v.w);
        }
    }
    __syncthreads();

    // ---- conv2 (k=3,p=1) + BN2 : fp32x2 lanes = (co, co+128), z via dup LDS.64 ----
    {
        const int cog = tid & 127;
        const int th  = tid >> 7;
        const int t0  = th * 16;
        ull acc[16];
        #pragma unroll
        for (int t = 0; t < 16; t++) acc[t] = 0ULL;

        const float* zb = zin + t0 * (2 * COUTC);     // row t0 => t = t0-1
        const ull* wbase = (const ull*)g_c2wt;

        for (int ci = 0; ci < COUTC; ci++) {
            ull w0 = wbase[(ci * 3 + 0) * 128 + cog];
            ull w1 = wbase[(ci * 3 + 1) * 128 + cog];
            ull w2 = wbase[(ci * 3 + 2) * 128 + cog];
            ull zz[18];
            #pragma unroll
            for (int j = 0; j < 18; j++)
                zz[j] = *(const ull*)(zb + j * (2 * COUTC) + 2 * ci);
            #pragma unroll
            for (int t = 0; t < 16; t++) {
                acc[t] = fma2(w0, zz[t],     acc[t]);
                acc[t] = fma2(w1, zz[t + 1], acc[t]);
                acc[t] = fma2(w2, zz[t + 2], acc[t]);
            }
        }
        const int coA = cog, coB = cog + 128;
        const float cbA = c2b[coA], mA = bn2m[coA], sA = g_bn2a[coA], bA = bn2b[coA];
        const float cbB = c2b[coB], mB = bn2m[coB], sB = g_bn2a[coB], bB = bn2b[coB];
        #pragma unroll
        for (int t = 0; t < 16; t++) {
            float2 v = upk2(acc[t]);
            int tt = t0 + t;
            bufA[coA * BSTR + tt] = fmaf((v.x + cbA) - mA, sA, bA);
            bufA[coB * BSTR + tt] = fmaf((v.y + cbB) - mB, sB, bB);
        }
    }
    __syncthreads();

    // ---- encoder CUBA LIF: thr 0.3, cd 0.9, vd 0.9 ----
    if (tid < COUTC) {
        float* row = bufA + tid * BSTR;
        const float cd = (float)(1.0 - 0.9);
        const float vd = (float)(1.0 - 0.9);
        float cur = 0.0f, vol = 0.0f;
        #pragma unroll 1
        for (int t = 0; t < TT; t++) {
            float xv = row[t];
            cur = fmaf(cd, cur, xv);
            vol = fmaf(vd, vol, cur);
            float s = ((vol - 0.3f) >= 0.0f) ? 1.0f : 0.0f;
            row[t] = s;
            vol = vol * (1.0f - s);
        }
        row[TT] = 0.0f;
    }
    __syncthreads();

    // ---- dense1: fp32x2 lanes = t-pairs, direct LDS.64 operands; write into zin region ----
    {
        const int og = tid & 127;
        const int th = tid >> 7;
        const int t0 = th * 16;
        ull a0[8], a1[8];
        #pragma unroll
        for (int p = 0; p < 8; p++) { a0[p] = 0ULL; a1[p] = 0ULL; }

        for (int c = 0; c < COUTC; c++) {
            float wa = g_d1wt[c * COUTC + og];
            float wb = g_d1wt[c * COUTC + og + 128];
            ull wap = pk2(wa, wa), wbp = pk2(wb, wb);
            const ull* sp = (const ull*)(bufA + c * BSTR + t0);
            #pragma unroll
            for (int p = 0; p < 8; p++) {
                ull s = sp[p];
                a0[p] = fma2(wap, s, a0[p]);
                a1[p] = fma2(wbp, s, a1[p]);
            }
        }
        ull* d0 = (ull*)(zin + og * BSTR + t0);
        ull* d1 = (ull*)(zin + (og + 128) * BSTR + t0);
        #pragma unroll
        for (int p = 0; p < 8; p++) { d0[p] = a0[p]; d1[p] = a1[p]; }
    }
    __syncthreads();

    // ---- dense1 CUBA LIF: thr 0.1, cd=1, vd=0.1 ----
    if (tid < COUTC) {
        float* row = zin + tid * BSTR;
        const float vdD = (float)(1.0 - 0.1);
        float vol = 0.0f;
        #pragma unroll 1
        for (int t = 0; t < TT; t++) {
            float xv = row[t];
            vol = fmaf(vdD, vol, xv);
            float s = ((vol - 0.1f) >= 0.0f) ? 1.0f : 0.0f;
            row[t] = s;
            vol = vol * (1.0f - s);
        }
    }
    __syncthreads();

    // ---- dense2: [2 x 256] ----
    if (tid < NCLS * TT) {
        int cls = tid / TT, t = tid - cls * TT;
        const float* w = d2w + cls * COUTC;
        float a = 0.0f;
        #pragma unroll 4
        for (int c = 0; c < COUTC; c++) a = fmaf(w[c], zin[c * BSTR + t], a);
        bufA[tid] = a;
    }
    __syncthreads();

    // ---- dense2 CUBA LIF + output ----
    if (tid < NCLS) {
        const float vdD = (float)(1.0 - 0.1);
        float vol = 0.0f;
        const float* rowi = bufA + tid * TT;
        float* rowo = out + (size_t)n * (NCLS * TT) + tid * TT;
        #pragma unroll 1
        for (int t = 0; t < TT; t++) {
            float xv = rowi[t];
            vol = fmaf(vdD, vol, xv);
            float s = ((vol - 0.1f) >= 0.0f) ? 1.0f : 0.0f;
            rowo[t] = s;
            vol = vol * (1.0f - s);
        }
    }
}

// ---------------- launch ----------------
extern "C" void kernel_launch(void* const* d_in, const int* in_sizes, int n_in,
                              void* d_out, int out_size)
{
    const float* x    = (const float*)d_in[0];
    const float* c1w  = (const float*)d_in[1];
    const float* c1b  = (const float*)d_in[2];
    const float* bn1g = (const float*)d_in[3];
    const float* bn1b = (const float*)d_in[4];
    const float* bn1m = (const float*)d_in[5];
    const float* bn1v = (const float*)d_in[6];
    const float* c2w  = (const float*)d_in[7];
    const float* c2b  = (const float*)d_in[8];
    const float* bn2g = (const float*)d_in[9];
    const float* bn2b = (const float*)d_in[10];
    const float* bn2m = (const float*)d_in[11];
    const float* bn2v = (const float*)d_in[12];
    const float* d1w  = (const float*)d_in[13];
    const float* d2w  = (const float*)d_in[14];
    float* out = (float*)d_out;

    const int smem_bytes = (ZROWS * 2 * COUTC + COUTC * BSTR) * (int)sizeof(float);
    cudaFuncSetAttribute(mega_kernel, cudaFuncAttributeMaxDynamicSharedMemorySize, smem_bytes);

    // conv1 first (self-contained) so the profiler's first-node capture shows it
    dim3 g1(126, 4);
    conv1_gemm<<<g1, 256>>>(x, c1w, c1b, bn1g, bn1b, bn1m, bn1v);

    prep_kernel<<<768, 256>>>(c2w, d1w, bn2g, bn2v);

    mega_kernel<<<BATCH, 512, smem_bytes>>>(c2b, bn2b, bn2m, d2w, out);
}

// round 5
// speedup vs baseline: 1.2121x; 1.0253x over previous
#include <cuda_runtime.h>
#include <math.h>

typedef unsigned long long ull;

#define BATCH 512
#define CIN   64
#define LIN   1024
#define COUTC 256
#define K1    32
#define STR1  16
#define TT    63
#define NCLS  2
#define KTOT  2048   // CIN*K1

#define ZROWS 66     // dup-z rows: t = -1 .. 64  (row = t+1), each row 512 floats (dup)
#define BSTR  66     // bufA / d1 row stride

// ---------------- device scratch ----------------
__device__ float g_z1[BATCH * TT * COUTC];       // [n][t][co]
__device__ float g_c2wt[COUTC * 3 * COUTC];      // [(ci*3+k)][2*cog+half]  (co pairs interleaved)
__device__ float g_d1wt[COUTC * COUTC];          // [c][o]
__device__ float g_bn2a[COUTC];

// ---------------- packed fp32x2 helpers ----------------
__device__ __forceinline__ ull pk2(float lo, float hi) {
    ull r; asm("mov.b64 %0, {%1,%2};" : "=l"(r) : "f"(lo), "f"(hi)); return r;
}
__device__ __forceinline__ ull fma2(ull a, ull b, ull c) {
    ull d; asm("fma.rn.f32x2 %0, %1, %2, %3;" : "=l"(d) : "l"(a), "l"(b), "l"(c)); return d;
}
__device__ __forceinline__ float2 upk2(ull v) {
    float2 f; asm("mov.b64 {%0,%1}, %2;" : "=f"(f.x), "=f"(f.y) : "l"(v)); return f;
}

// ---------------- conv1 (im2col GEMM, M=32256 K=2048 N=256) + BN1 ----------------
// Block tile 128(M) x 128(N) x 16(K). 8 warps in 4(M)x2(N); warp tile 32x64.
// Lane grid 4(mq) x 8(nq), micro-tile 8x8: A reads 8-lane-shared (4 distinct
// addrs per LDS.128), B reads 4-lane-shared ull pairs -> minimal crossbar.
__global__ __launch_bounds__(256, 2)
void conv1_gemm(const float* __restrict__ x,
                const float* __restrict__ c1w,
                const float* __restrict__ c1b,
                const float* __restrict__ bn1g,
                const float* __restrict__ bn1b,
                const float* __restrict__ bn1m,
                const float* __restrict__ bn1v)
{
    __shared__ __align__(16) float As[2][16][128];
    __shared__ __align__(16) float Bs[2][16][128];
    const int tid  = threadIdx.x;
    const int lane = tid & 31;
    const int w    = tid >> 5;
    const int mBase = blockIdx.x * 128;
    const int nBase = blockIdx.y * 128;

    const int warp_m = (w & 3) * 32;
    const int warp_n = (w >> 2) * 64;
    const int mq = (lane >> 3) * 8;
    const int nq = (lane & 7) * 8;

    // ---- A loader: m = tid&127, khalf = (tid>>7)*8 ----
    const int am    = tid & 127;
    const int akh   = (tid >> 7) * 8;
    const int m_row = mBase + am;
    const int n_idx = m_row / TT;
    const int t_idx = m_row - n_idx * TT;
    const float* xrow = x + ((size_t)n_idx * CIN) * LIN + t_idx * STR1;

    // ---- B loader: co = tid&127, khalf = (tid>>7)*8 ----
    const float* wrow = c1w + (size_t)(nBase + am) * KTOT;

    ull acc[8][4];
    #pragma unroll
    for (int i = 0; i < 8; i++)
        #pragma unroll
        for (int j = 0; j < 4; j++) acc[i][j] = 0ULL;

    float4 ap0, ap1, bp0, bp1;

    #define LOAD_REGS(KB) {                                                    \
        int col = (KB) + akh;                                                  \
        const float* abase = xrow + (size_t)(col >> 5) * LIN + (col & 31);     \
        ap0 = *(const float4*)(abase);                                         \
        ap1 = *(const float4*)(abase + 4);                                     \
        bp0 = *(const float4*)(wrow + col);                                    \
        bp1 = *(const float4*)(wrow + col + 4);                                \
    }
    #define STORE_SMEM(B) {                                                    \
        As[B][akh + 0][am] = ap0.x; As[B][akh + 1][am] = ap0.y;                \
        As[B][akh + 2][am] = ap0.z; As[B][akh + 3][am] = ap0.w;                \
        As[B][akh + 4][am] = ap1.x; As[B][akh + 5][am] = ap1.y;                \
        As[B][akh + 6][am] = ap1.z; As[B][akh + 7][am] = ap1.w;                \
        Bs[B][akh + 0][am] = bp0.x; Bs[B][akh + 1][am] = bp0.y;                \
        Bs[B][akh + 2][am] = bp0.z; Bs[B][akh + 3][am] = bp0.w;                \
        Bs[B][akh + 4][am] = bp1.x; Bs[B][akh + 5][am] = bp1.y;                \
        Bs[B][akh + 6][am] = bp1.z; Bs[B][akh + 7][am] = bp1.w;                \
    }

    LOAD_REGS(0);
    STORE_SMEM(0);
    __syncthreads();

    int buf = 0;
    for (int kb = 0; kb < KTOT; kb += 16) {
        const bool more = (kb + 16) < KTOT;
        if (more) LOAD_REGS(kb + 16);

        const float (*A)[128] = As[buf];
        const float (*B)[128] = Bs[buf];
        #pragma unroll
        for (int kk = 0; kk < 16; kk++) {
            float4 x0 = *(const float4*)&A[kk][warp_m + mq];
            float4 x1 = *(const float4*)&A[kk][warp_m + mq + 4];
            ulonglong2 q0 = *(const ulonglong2*)&B[kk][warp_n + nq];
            ulonglong2 q1 = *(const ulonglong2*)&B[kk][warp_n + nq + 4];
            ull b0 = q0.x, b1 = q0.y, b2 = q1.x, b3 = q1.y;
            ull ap;
            #define FMA_ROW(I, AV)                        \
                ap = pk2(AV, AV);                         \
                acc[I][0] = fma2(ap, b0, acc[I][0]);      \
                acc[I][1] = fma2(ap, b1, acc[I][1]);      \
                acc[I][2] = fma2(ap, b2, acc[I][2]);      \
                acc[I][3] = fma2(ap, b3, acc[I][3]);
            FMA_ROW(0, x0.x) FMA_ROW(1, x0.y) FMA_ROW(2, x0.z) FMA_ROW(3, x0.w)
            FMA_ROW(4, x1.x) FMA_ROW(5, x1.y) FMA_ROW(6, x1.z) FMA_ROW(7, x1.w)
            #undef FMA_ROW
        }
        if (more) STORE_SMEM(buf ^ 1);
        __syncthreads();
        buf ^= 1;
    }
    #undef LOAD_REGS
    #undef STORE_SMEM

    // epilogue: ((conv + b) - m) * (g/sqrt(v+eps)) + beta  -> g_z1 [n][t][co]
    float sc[8], bb[8], mm[8], cb[8];
    #pragma unroll
    for (int jj = 0; jj < 8; jj++) {
        int co = nBase + warp_n + nq + jj;
        sc[jj] = bn1g[co] / sqrtf(bn1v[co] + 1e-5f);
        bb[jj] = bn1b[co]; mm[jj] = bn1m[co]; cb[jj] = c1b[co];
    }
    #pragma unroll
    for (int i = 0; i < 8; i++) {
        int m = mBase + warp_m + mq + i;
        float o_[8];
        #pragma unroll
        for (int j = 0; j < 4; j++) {
            float2 v = upk2(acc[i][j]);
            o_[2 * j] = v.x; o_[2 * j + 1] = v.y;
        }
        #pragma unroll
        for (int jj = 0; jj < 8; jj++) {
            float t1 = (o_[jj] + cb[jj]) - mm[jj];
            o_[jj] = fmaf(t1, sc[jj], bb[jj]);
        }
        float* dst = g_z1 + (size_t)m * COUTC + nBase + warp_n + nq;
        *(float4*)dst       = make_float4(o_[0], o_[1], o_[2], o_[3]);
        *(float4*)(dst + 4) = make_float4(o_[4], o_[5], o_[6], o_[7]);
    }
}

// ---------------- prep: conv2/dense1 weight layouts + BN2 scale ----------------
__global__ void prep_kernel(const float* __restrict__ c2w,
                            const float* __restrict__ d1w,
                            const float* __restrict__ bn2g, const float* __restrict__ bn2v)
{
    int i = blockIdx.x * blockDim.x + threadIdx.x;
    if (i < COUTC * 3 * COUTC) {                  // conv2 w: pair-interleaved
        int row = i >> 8, j = i & 255;
        int ci = row / 3, k = row - 3 * ci;
        int co = (j >> 1) + 128 * (j & 1);
        g_c2wt[i] = c2w[(co * COUTC + ci) * 3 + k];
    }
    if (i < COUTC * COUTC) {                      // dense w1: [o][c] -> [c][o]
        int c = i >> 8, o = i & 255;
        g_d1wt[i] = d1w[o * COUTC + c];
    }
    if (i < COUTC) {
        g_bn2a[i] = bn2g[i] / sqrtf(bn2v[i] + 1e-5f);
    }
}

// ---------------- mega kernel ----------------
__global__ __launch_bounds__(512, 1)
void mega_kernel(const float* __restrict__ c2b,
                 const float* __restrict__ bn2b,
                 const float* __restrict__ bn2m,
                 const float* __restrict__ d2w,
                 float* __restrict__ out)
{
    extern __shared__ float sm[];
    float* zin  = sm;                          // dup-z: [row 0..65][512] ; later reused [o][BSTR]
    float* bufA = sm + ZROWS * 2 * COUTC;      // [co][BSTR]

    const int n = blockIdx.x;
    const int tid = threadIdx.x;

    // ---- load z1[n] into dup rows 1..63; zero rows 0,64,65 ----
    {
        float4* z4 = (float4*)zin;                                  // row 0: 512 floats
        for (int i = tid; i < (2 * COUTC) / 4; i += 512) z4[i] = make_float4(0, 0, 0, 0);
        float4* zp4 = (float4*)(zin + 64 * 2 * COUTC);              // rows 64,65: 1024 floats
        for (int i = tid; i < (4 * COUTC) / 4; i += 512) zp4[i] = make_float4(0, 0, 0, 0);
        const float4* src = (const float4*)(g_z1 + (size_t)n * (TT * COUTC));
        float4* dstv = (float4*)(zin + 2 * COUTC);                  // row 1 start
        for (int i = tid; i < (TT * COUTC) / 4; i += 512) {
            float4 v = src[i];
            dstv[2 * i]     = make_float4(v.x, v.x, v.y, v.y);
            dstv[2 * i + 1] = make_float4(v.z, v.z, v.w, v.w);
        }
    }
    __syncthreads();

    // ---- conv2 (k=3,p=1) + BN2 : fp32x2 lanes = (co, co+128), prefetched weights ----
    {
        const int cog = tid & 127;
        const int th  = tid >> 7;
        const int t0  = th * 16;
        ull acc[16];
        #pragma unroll
        for (int t = 0; t < 16; t++) acc[t] = 0ULL;

        const float* zb = zin + t0 * (2 * COUTC);     // row t0 => t = t0-1
        const ull* wb = (const ull*)g_c2wt;

        ull w0 = wb[cog], w1 = wb[128 + cog], w2 = wb[256 + cog];
        #pragma unroll 2
        for (int ci = 0; ci < COUTC; ci++) {
            // prefetch next ci's weights (wrap at end; harmless reload)
            const int cin = (ci + 1) & 255;
            const ull* wn = wb + cin * 384;
            ull nw0 = wn[cog], nw1 = wn[128 + cog], nw2 = wn[256 + cog];

            ull zz[18];
            #pragma unroll
            for (int j = 0; j < 18; j++)
                zz[j] = *(const ull*)(zb + j * (2 * COUTC) + 2 * ci);
            #pragma unroll
            for (int t = 0; t < 16; t++) {
                acc[t] = fma2(w0, zz[t],     acc[t]);
                acc[t] = fma2(w1, zz[t + 1], acc[t]);
                acc[t] = fma2(w2, zz[t + 2], acc[t]);
            }
            w0 = nw0; w1 = nw1; w2 = nw2;
        }
        const int coA = cog, coB = cog + 128;
        const float cbA = c2b[coA], mA = bn2m[coA], sA = g_bn2a[coA], bA = bn2b[coA];
        const float cbB = c2b[coB], mB = bn2m[coB], sB = g_bn2a[coB], bB = bn2b[coB];
        #pragma unroll
        for (int t = 0; t < 16; t++) {
            float2 v = upk2(acc[t]);
            int tt = t0 + t;
            bufA[coA * BSTR + tt] = fmaf((v.x + cbA) - mA, sA, bA);
            bufA[coB * BSTR + tt] = fmaf((v.y + cbB) - mB, sB, bB);
        }
    }
    __syncthreads();

    // ---- encoder CUBA LIF: thr 0.3, cd 0.9, vd 0.9 ----
    if (tid < COUTC) {
        float* row = bufA + tid * BSTR;
        const float cd = (float)(1.0 - 0.9);
        const float vd = (float)(1.0 - 0.9);
        float cur = 0.0f, vol = 0.0f;
        #pragma unroll 1
        for (int t = 0; t < TT; t++) {
            float xv = row[t];
            cur = fmaf(cd, cur, xv);
            vol = fmaf(vd, vol, cur);
            float s = ((vol - 0.3f) >= 0.0f) ? 1.0f : 0.0f;
            row[t] = s;
            vol = vol * (1.0f - s);
        }
        row[TT] = 0.0f;
    }
    __syncthreads();

    // ---- dense1: fp32x2 lanes = t-pairs, prefetched weights ----
    {
        const int og = tid & 127;
        const int th = tid >> 7;
        const int t0 = th * 16;
        ull a0[8], a1[8];
        #pragma unroll
        for (int p = 0; p < 8; p++) { a0[p] = 0ULL; a1[p] = 0ULL; }

        float wa = g_d1wt[og], wbv = g_d1wt[og + 128];
        #pragma unroll 2
        for (int c = 0; c < COUTC; c++) {
            const int cn = (c + 1) & 255;
            float nwa = g_d1wt[cn * COUTC + og];
            float nwb = g_d1wt[cn * COUTC + og + 128];

            ull wap = pk2(wa, wa), wbp = pk2(wbv, wbv);
            const ull* sp = (const ull*)(bufA + c * BSTR + t0);
            #pragma unroll
            for (int p = 0; p < 8; p++) {
                ull s = sp[p];
                a0[p] = fma2(wap, s, a0[p]);
                a1[p] = fma2(wbp, s, a1[p]);
            }
            wa = nwa; wbv = nwb;
        }
        ull* d0 = (ull*)(zin + og * BSTR + t0);
        ull* d1 = (ull*)(zin + (og + 128) * BSTR + t0);
        #pragma unroll
        for (int p = 0; p < 8; p++) { d0[p] = a0[p]; d1[p] = a1[p]; }
    }
    __syncthreads();

    // ---- dense1 CUBA LIF: thr 0.1, cd=1, vd=0.1 ----
    if (tid < COUTC) {
        float* row = zin + tid * BSTR;
        const float vdD = (float)(1.0 - 0.1);
        float vol = 0.0f;
        #pragma unroll 1
        for (int t = 0; t < TT; t++) {
            float xv = row[t];
            vol = fmaf(vdD, vol, xv);
            float s = ((vol - 0.1f) >= 0.0f) ? 1.0f : 0.0f;
            row[t] = s;
            vol = vol * (1.0f - s);
        }
    }
    __syncthreads();

    // ---- dense2: [2 x 256] ----
    if (tid < NCLS * TT) {
        int cls = tid / TT, t = tid - cls * TT;
        const float* w = d2w + cls * COUTC;
        float a = 0.0f;
        #pragma unroll 4
        for (int c = 0; c < COUTC; c++) a = fmaf(w[c], zin[c * BSTR + t], a);
        bufA[tid] = a;
    }
    __syncthreads();

    // ---- dense2 CUBA LIF + output ----
    if (tid < NCLS) {
        const float vdD = (float)(1.0 - 0.1);
        float vol = 0.0f;
        const float* rowi = bufA + tid * TT;
        float* rowo = out + (size_t)n * (NCLS * TT) + tid * TT;
        #pragma unroll 1
        for (int t = 0; t < TT; t++) {
            float xv = rowi[t];
            vol = fmaf(vdD, vol, xv);
            float s = ((vol - 0.1f) >= 0.0f) ? 1.0f : 0.0f;
            rowo[t] = s;
            vol = vol * (1.0f - s);
        }
    }
}

// ---------------- launch ----------------
extern "C" void kernel_launch(void* const* d_in, const int* in_sizes, int n_in,
                              void* d_out, int out_size)
{
    const float* x    = (const float*)d_in[0];
    const float* c1w  = (const float*)d_in[1];
    const float* c1b  = (const float*)d_in[2];
    const float* bn1g = (const float*)d_in[3];
    const float* bn1b = (const float*)d_in[4];
    const float* bn1m = (const float*)d_in[5];
    const float* bn1v = (const float*)d_in[6];
    const float* c2w  = (const float*)d_in[7];
    const float* c2b  = (const float*)d_in[8];
    const float* bn2g = (const float*)d_in[9];
    const float* bn2b = (const float*)d_in[10];
    const float* bn2m = (const float*)d_in[11];
    const float* bn2v = (const float*)d_in[12];
    const float* d1w  = (const float*)d_in[13];
    const float* d2w  = (const float*)d_in[14];
    float* out = (float*)d_out;

    const int smem_bytes = (ZROWS * 2 * COUTC + COUTC * BSTR) * (int)sizeof(float);
    cudaFuncSetAttribute(mega_kernel, cudaFuncAttributeMaxDynamicSharedMemorySize, smem_bytes);

    // conv1 first (self-contained) so the profiler's first-node capture shows it
    dim3 g1(252, 2);
    conv1_gemm<<<g1, 256>>>(x, c1w, c1b, bn1g, bn1b, bn1m, bn1v);

    prep_kernel<<<768, 256>>>(c2w, d1w, bn2g, bn2v);

    mega_kernel<<<BATCH, 512, smem_bytes>>>(c2b, bn2b, bn2m, d2w, out);
}

// round 6
// speedup vs baseline: 1.2679x; 1.0460x over previous
#include <cuda_runtime.h>
#include <math.h>

typedef unsigned long long ull;

#define BATCH 512
#define CIN   64
#define LIN   1024
#define COUTC 256
#define K1    32
#define STR1  16
#define TT    63
#define NCLS  2
#define KTOT  2048   // CIN*K1

#define ZROWS 66     // dup-z rows: t = -1 .. 64  (row = t+1), each row 512 floats (dup)
#define BSTR  66     // bufA / d1 row stride

// ---------------- device scratch ----------------
__device__ float g_z1[BATCH * TT * COUTC];       // [n][t][co]
__device__ float g_c2wt[COUTC * 3 * COUTC];      // [(ci*3+k)][2*cog+half]  (co pairs interleaved)
__device__ float g_d1wt[COUTC * COUTC];          // [c][o]
__device__ float g_bn2a[COUTC];

// ---------------- packed fp32x2 helpers ----------------
__device__ __forceinline__ ull pk2(float lo, float hi) {
    ull r; asm("mov.b64 %0, {%1,%2};" : "=l"(r) : "f"(lo), "f"(hi)); return r;
}
__device__ __forceinline__ ull fma2(ull a, ull b, ull c) {
    ull d; asm("fma.rn.f32x2 %0, %1, %2, %3;" : "=l"(d) : "l"(a), "l"(b), "l"(c)); return d;
}
__device__ __forceinline__ float2 upk2(ull v) {
    float2 f; asm("mov.b64 {%0,%1}, %2;" : "=f"(f.x), "=f"(f.y) : "l"(v)); return f;
}

// ---------------- conv1 (im2col GEMM, M=32256 K=2048 N=256) + BN1 ----------------
// 128 threads, block tile 128(M)x128(N)x16(K). 4 warps in 2(M)x2(N) -> warp 64x64.
// Lane grid 8(mq) x 4(nq), micro-tile 8Mx16N: per kk per warp only 6 LDS.128
// (3072B write-back) vs 64 fma2 -> fma-pipe bound, not LDS-bound.
__global__ __launch_bounds__(128, 2)
void conv1_gemm(const float* __restrict__ x,
                const float* __restrict__ c1w,
                const float* __restrict__ c1b,
                const float* __restrict__ bn1g,
                const float* __restrict__ bn1b,
                const float* __restrict__ bn1m,
                const float* __restrict__ bn1v)
{
    __shared__ __align__(16) float As[2][16][128];
    __shared__ __align__(16) float Bs[2][16][128];
    const int tid  = threadIdx.x;
    const int lane = tid & 31;
    const int w    = tid >> 5;
    const int mBase = blockIdx.x * 128;
    const int nBase = blockIdx.y * 128;

    const int warp_m = (w & 1) * 64;
    const int warp_n = (w >> 1) * 64;
    const int mq = (lane >> 2) * 8;      // 0..56
    const int nq = (lane & 3) * 16;      // 0..48

    // ---- A loader: thread tid loads 16 consecutive k for im2col row (mBase+tid)
    const int m_row = mBase + tid;
    const int n_idx = m_row / TT;
    const int t_idx = m_row - n_idx * TT;
    const float* xrow = x + ((size_t)n_idx * CIN) * LIN + t_idx * STR1;

    // ---- B loader: thread tid loads 16 consecutive k for co (nBase+tid)
    const float* wrow = c1w + (size_t)(nBase + tid) * KTOT;

    ull acc[8][8];
    #pragma unroll
    for (int i = 0; i < 8; i++)
        #pragma unroll
        for (int j = 0; j < 8; j++) acc[i][j] = 0ULL;

    float4 ap0, ap1, ap2, ap3, bq0, bq1, bq2, bq3;

    #define LOAD_REGS(KB) {                                                    \
        const float* abase = xrow + (size_t)((KB) >> 5) * LIN + ((KB) & 31);   \
        ap0 = *(const float4*)(abase);                                         \
        ap1 = *(const float4*)(abase + 4);                                     \
        ap2 = *(const float4*)(abase + 8);                                     \
        ap3 = *(const float4*)(abase + 12);                                    \
        bq0 = *(const float4*)(wrow + (KB));                                   \
        bq1 = *(const float4*)(wrow + (KB) + 4);                               \
        bq2 = *(const float4*)(wrow + (KB) + 8);                               \
        bq3 = *(const float4*)(wrow + (KB) + 12);                              \
    }
    #define STORE_SMEM(B) {                                                    \
        As[B][0][tid]  = ap0.x; As[B][1][tid]  = ap0.y;                        \
        As[B][2][tid]  = ap0.z; As[B][3][tid]  = ap0.w;                        \
        As[B][4][tid]  = ap1.x; As[B][5][tid]  = ap1.y;                        \
        As[B][6][tid]  = ap1.z; As[B][7][tid]  = ap1.w;                        \
        As[B][8][tid]  = ap2.x; As[B][9][tid]  = ap2.y;                        \
        As[B][10][tid] = ap2.z; As[B][11][tid] = ap2.w;                        \
        As[B][12][tid] = ap3.x; As[B][13][tid] = ap3.y;                        \
        As[B][14][tid] = ap3.z; As[B][15][tid] = ap3.w;                        \
        Bs[B][0][tid]  = bq0.x; Bs[B][1][tid]  = bq0.y;                        \
        Bs[B][2][tid]  = bq0.z; Bs[B][3][tid]  = bq0.w;                        \
        Bs[B][4][tid]  = bq1.x; Bs[B][5][tid]  = bq1.y;                        \
        Bs[B][6][tid]  = bq1.z; Bs[B][7][tid]  = bq1.w;                        \
        Bs[B][8][tid]  = bq2.x; Bs[B][9][tid]  = bq2.y;                        \
        Bs[B][10][tid] = bq2.z; Bs[B][11][tid] = bq2.w;                        \
        Bs[B][12][tid] = bq3.x; Bs[B][13][tid] = bq3.y;                        \
        Bs[B][14][tid] = bq3.z; Bs[B][15][tid] = bq3.w;                        \
    }

    LOAD_REGS(0);
    STORE_SMEM(0);
    __syncthreads();

    int buf = 0;
    for (int kb = 0; kb < KTOT; kb += 16) {
        const bool more = (kb + 16) < KTOT;
        if (more) LOAD_REGS(kb + 16);

        const float (*A)[128] = As[buf];
        const float (*B)[128] = Bs[buf];
        #pragma unroll
        for (int kk = 0; kk < 16; kk++) {
            float4 x0 = *(const float4*)&A[kk][warp_m + mq];
            float4 x1 = *(const float4*)&A[kk][warp_m + mq + 4];
            ulonglong2 q0 = *(const ulonglong2*)&B[kk][warp_n + nq];
            ulonglong2 q1 = *(const ulonglong2*)&B[kk][warp_n + nq + 4];
            ulonglong2 q2 = *(const ulonglong2*)&B[kk][warp_n + nq + 8];
            ulonglong2 q3 = *(const ulonglong2*)&B[kk][warp_n + nq + 12];
            ull ap;
            #define FMA_ROW(I, AV)                        \
                ap = pk2(AV, AV);                         \
                acc[I][0] = fma2(ap, q0.x, acc[I][0]);    \
                acc[I][1] = fma2(ap, q0.y, acc[I][1]);    \
                acc[I][2] = fma2(ap, q1.x, acc[I][2]);    \
                acc[I][3] = fma2(ap, q1.y, acc[I][3]);    \
                acc[I][4] = fma2(ap, q2.x, acc[I][4]);    \
                acc[I][5] = fma2(ap, q2.y, acc[I][5]);    \
                acc[I][6] = fma2(ap, q3.x, acc[I][6]);    \
                acc[I][7] = fma2(ap, q3.y, acc[I][7]);
            FMA_ROW(0, x0.x) FMA_ROW(1, x0.y) FMA_ROW(2, x0.z) FMA_ROW(3, x0.w)
            FMA_ROW(4, x1.x) FMA_ROW(5, x1.y) FMA_ROW(6, x1.z) FMA_ROW(7, x1.w)
            #undef FMA_ROW
        }
        if (more) STORE_SMEM(buf ^ 1);
        __syncthreads();
        buf ^= 1;
    }
    #undef LOAD_REGS
    #undef STORE_SMEM

    // epilogue: ((conv + b) - m) * (g/sqrt(v+eps)) + beta  -> g_z1 [n][t][co]
    float sc[16], bb[16], mm[16], cb[16];
    #pragma unroll
    for (int jj = 0; jj < 16; jj++) {
        int co = nBase + warp_n + nq + jj;
        sc[jj] = bn1g[co] / sqrtf(bn1v[co] + 1e-5f);
        bb[jj] = bn1b[co]; mm[jj] = bn1m[co]; cb[jj] = c1b[co];
    }
    #pragma unroll
    for (int i = 0; i < 8; i++) {
        int m = mBase + warp_m + mq + i;
        float o_[16];
        #pragma unroll
        for (int j = 0; j < 8; j++) {
            float2 v = upk2(acc[i][j]);
            o_[2 * j] = v.x; o_[2 * j + 1] = v.y;
        }
        #pragma unroll
        for (int jj = 0; jj < 16; jj++) {
            float t1 = (o_[jj] + cb[jj]) - mm[jj];
            o_[jj] = fmaf(t1, sc[jj], bb[jj]);
        }
        float* dst = g_z1 + (size_t)m * COUTC + nBase + warp_n + nq;
        *(float4*)(dst)      = make_float4(o_[0],  o_[1],  o_[2],  o_[3]);
        *(float4*)(dst + 4)  = make_float4(o_[4],  o_[5],  o_[6],  o_[7]);
        *(float4*)(dst + 8)  = make_float4(o_[8],  o_[9],  o_[10], o_[11]);
        *(float4*)(dst + 12) = make_float4(o_[12], o_[13], o_[14], o_[15]);
    }
}

// ---------------- prep: conv2/dense1 weight layouts + BN2 scale ----------------
__global__ void prep_kernel(const float* __restrict__ c2w,
                            const float* __restrict__ d1w,
                            const float* __restrict__ bn2g, const float* __restrict__ bn2v)
{
    int i = blockIdx.x * blockDim.x + threadIdx.x;
    if (i < COUTC * 3 * COUTC) {                  // conv2 w: pair-interleaved
        int row = i >> 8, j = i & 255;
        int ci = row / 3, k = row - 3 * ci;
        int co = (j >> 1) + 128 * (j & 1);
        g_c2wt[i] = c2w[(co * COUTC + ci) * 3 + k];
    }
    if (i < COUTC * COUTC) {                      // dense w1: [o][c] -> [c][o]
        int c = i >> 8, o = i & 255;
        g_d1wt[i] = d1w[o * COUTC + c];
    }
    if (i < COUTC) {
        g_bn2a[i] = bn2g[i] / sqrtf(bn2v[i] + 1e-5f);
    }
}

// ---------------- mega kernel ----------------
__global__ __launch_bounds__(512, 1)
void mega_kernel(const float* __restrict__ c2b,
                 const float* __restrict__ bn2b,
                 const float* __restrict__ bn2m,
                 const float* __restrict__ d2w,
                 float* __restrict__ out)
{
    extern __shared__ float sm[];
    float* zin  = sm;                          // dup-z: [row 0..65][512] ; later reused [o][BSTR]
    float* bufA = sm + ZROWS * 2 * COUTC;      // [co][BSTR]

    const int n = blockIdx.x;
    const int tid = threadIdx.x;

    // ---- load z1[n] into dup rows 1..63; zero rows 0,64,65 ----
    {
        float4* z4 = (float4*)zin;                                  // row 0: 512 floats
        for (int i = tid; i < (2 * COUTC) / 4; i += 512) z4[i] = make_float4(0, 0, 0, 0);
        float4* zp4 = (float4*)(zin + 64 * 2 * COUTC);              // rows 64,65: 1024 floats
        for (int i = tid; i < (4 * COUTC) / 4; i += 512) zp4[i] = make_float4(0, 0, 0, 0);
        const float4* src = (const float4*)(g_z1 + (size_t)n * (TT * COUTC));
        float4* dstv = (float4*)(zin + 2 * COUTC);                  // row 1 start
        for (int i = tid; i < (TT * COUTC) / 4; i += 512) {
            float4 v = src[i];
            dstv[2 * i]     = make_float4(v.x, v.x, v.y, v.y);
            dstv[2 * i + 1] = make_float4(v.z, v.z, v.w, v.w);
        }
    }
    __syncthreads();

    // ---- conv2 (k=3,p=1) + BN2 : fp32x2 lanes = (co, co+128), prefetched weights ----
    {
        const int cog = tid & 127;
        const int th  = tid >> 7;
        const int t0  = th * 16;
        ull acc[16];
        #pragma unroll
        for (int t = 0; t < 16; t++) acc[t] = 0ULL;

        const float* zb = zin + t0 * (2 * COUTC);     // row t0 => t = t0-1
        const ull* wb = (const ull*)g_c2wt;

        ull w0 = wb[cog], w1 = wb[128 + cog], w2 = wb[256 + cog];
        #pragma unroll 2
        for (int ci = 0; ci < COUTC; ci++) {
            // prefetch next ci's weights (wrap at end; harmless reload)
            const int cin = (ci + 1) & 255;
            const ull* wn = wb + cin * 384;
            ull nw0 = wn[cog], nw1 = wn[128 + cog], nw2 = wn[256 + cog];

            ull zz[18];
            #pragma unroll
            for (int j = 0; j < 18; j++)
                zz[j] = *(const ull*)(zb + j * (2 * COUTC) + 2 * ci);
            #pragma unroll
            for (int t = 0; t < 16; t++) {
                acc[t] = fma2(w0, zz[t],     acc[t]);
                acc[t] = fma2(w1, zz[t + 1], acc[t]);
                acc[t] = fma2(w2, zz[t + 2], acc[t]);
            }
            w0 = nw0; w1 = nw1; w2 = nw2;
        }
        const int coA = cog, coB = cog + 128;
        const float cbA = c2b[coA], mA = bn2m[coA], sA = g_bn2a[coA], bA = bn2b[coA];
        const float cbB = c2b[coB], mB = bn2m[coB], sB = g_bn2a[coB], bB = bn2b[coB];
        #pragma unroll
        for (int t = 0; t < 16; t++) {
            float2 v = upk2(acc[t]);
            int tt = t0 + t;
            bufA[coA * BSTR + tt] = fmaf((v.x + cbA) - mA, sA, bA);
            bufA[coB * BSTR + tt] = fmaf((v.y + cbB) - mB, sB, bB);
        }
    }
    __syncthreads();

    // ---- encoder CUBA LIF: thr 0.3, cd 0.9, vd 0.9 ----
    if (tid < COUTC) {
        float* row = bufA + tid * BSTR;
        const float cd = (float)(1.0 - 0.9);
        const float vd = (float)(1.0 - 0.9);
        float cur = 0.0f, vol = 0.0f;
        #pragma unroll 1
        for (int t = 0; t < TT; t++) {
            float xv = row[t];
            cur = fmaf(cd, cur, xv);
            vol = fmaf(vd, vol, cur);
            float s = ((vol - 0.3f) >= 0.0f) ? 1.0f : 0.0f;
            row[t] = s;
            vol = vol * (1.0f - s);
        }
        row[TT] = 0.0f;
    }
    __syncthreads();

    // ---- dense1: fp32x2 lanes = t-pairs, prefetched weights ----
    {
        const int og = tid & 127;
        const int th = tid >> 7;
        const int t0 = th * 16;
        ull a0[8], a1[8];
        #pragma unroll
        for (int p = 0; p < 8; p++) { a0[p] = 0ULL; a1[p] = 0ULL; }

        float wa = g_d1wt[og], wbv = g_d1wt[og + 128];
        #pragma unroll 2
        for (int c = 0; c < COUTC; c++) {
            const int cn = (c + 1) & 255;
            float nwa = g_d1wt[cn * COUTC + og];
            float nwb = g_d1wt[cn * COUTC + og + 128];

            ull wap = pk2(wa, wa), wbp = pk2(wbv, wbv);
            const ull* sp = (const ull*)(bufA + c * BSTR + t0);
            #pragma unroll
            for (int p = 0; p < 8; p++) {
                ull s = sp[p];
                a0[p] = fma2(wap, s, a0[p]);
                a1[p] = fma2(wbp, s, a1[p]);
            }
            wa = nwa; wbv = nwb;
        }
        ull* d0 = (ull*)(zin + og * BSTR + t0);
        ull* d1 = (ull*)(zin + (og + 128) * BSTR + t0);
        #pragma unroll
        for (int p = 0; p < 8; p++) { d0[p] = a0[p]; d1[p] = a1[p]; }
    }
    __syncthreads();

    // ---- dense1 CUBA LIF: thr 0.1, cd=1, vd=0.1 ----
    if (tid < COUTC) {
        float* row = zin + tid * BSTR;
        const float vdD = (float)(1.0 - 0.1);
        float vol = 0.0f;
        #pragma unroll 1
        for (int t = 0; t < TT; t++) {
            float xv = row[t];
            vol = fmaf(vdD, vol, xv);
            float s = ((vol - 0.1f) >= 0.0f) ? 1.0f : 0.0f;
            row[t] = s;
            vol = vol * (1.0f - s);
        }
    }
    __syncthreads();

    // ---- dense2: [2 x 256] ----
    if (tid < NCLS * TT) {
        int cls = tid / TT, t = tid - cls * TT;
        const float* w = d2w + cls * COUTC;
        float a = 0.0f;
        #pragma unroll 4
        for (int c = 0; c < COUTC; c++) a = fmaf(w[c], zin[c * BSTR + t], a);
        bufA[tid] = a;
    }
    __syncthreads();

    // ---- dense2 CUBA LIF + output ----
    if (tid < NCLS) {
        const float vdD = (float)(1.0 - 0.1);
        float vol = 0.0f;
        const float* rowi = bufA + tid * TT;
        float* rowo = out + (size_t)n * (NCLS * TT) + tid * TT;
        #pragma unroll 1
        for (int t = 0; t < TT; t++) {
            float xv = rowi[t];
            vol = fmaf(vdD, vol, xv);
            float s = ((vol - 0.1f) >= 0.0f) ? 1.0f : 0.0f;
            rowo[t] = s;
            vol = vol * (1.0f - s);
        }
    }
}

// ---------------- launch ----------------
extern "C" void kernel_launch(void* const* d_in, const int* in_sizes, int n_in,
                              void* d_out, int out_size)
{
    const float* x    = (const float*)d_in[0];
    const float* c1w  = (const float*)d_in[1];
    const float* c1b  = (const float*)d_in[2];
    const float* bn1g = (const float*)d_in[3];
    const float* bn1b = (const float*)d_in[4];
    const float* bn1m = (const float*)d_in[5];
    const float* bn1v = (const float*)d_in[6];
    const float* c2w  = (const float*)d_in[7];
    const float* c2b  = (const float*)d_in[8];
    const float* bn2g = (const float*)d_in[9];
    const float* bn2b = (const float*)d_in[10];
    const float* bn2m = (const float*)d_in[11];
    const float* bn2v = (const float*)d_in[12];
    const float* d1w  = (const float*)d_in[13];
    const float* d2w  = (const float*)d_in[14];
    float* out = (float*)d_out;

    const int smem_bytes = (ZROWS * 2 * COUTC + COUTC * BSTR) * (int)sizeof(float);
    cudaFuncSetAttribute(mega_kernel, cudaFuncAttributeMaxDynamicSharedMemorySize, smem_bytes);

    // conv1 first (self-contained) so the profiler's first-node capture shows it
    dim3 g1(252, 2);
    conv1_gemm<<<g1, 128>>>(x, c1w, c1b, bn1g, bn1b, bn1m, bn1v);

    prep_kernel<<<768, 256>>>(c2w, d1w, bn2g, bn2v);

    mega_kernel<<<BATCH, 512, smem_bytes>>>(c2b, bn2b, bn2m, d2w, out);
}

// round 7
// speedup vs baseline: 1.2685x; 1.0005x over previous
#include <cuda_runtime.h>
#include <math.h>

typedef unsigned long long ull;

#define BATCH 512
#define CIN   64
#define LIN   1024
#define COUTC 256
#define K1    32
#define STR1  16
#define TT    63
#define NCLS  2
#define KTOT  2048   // CIN*K1

#define ZROWS 66     // dup-z rows: t = -1 .. 64  (row = t+1), each row 512 floats (dup)
#define BSTR  66     // bufA / d1 row stride

// ---------------- device scratch ----------------
__device__ float g_z1[BATCH * TT * COUTC];       // [n][t][co]
__device__ float g_c2wt[COUTC * 3 * COUTC];      // [(ci*3+k)][2*cog+half]  (co pairs interleaved)
__device__ float g_d1wt[COUTC * COUTC];          // [c][o]
__device__ float g_bn2a[COUTC];

// ---------------- packed fp32x2 helpers ----------------
__device__ __forceinline__ ull pk2(float lo, float hi) {
    ull r; asm("mov.b64 %0, {%1,%2};" : "=l"(r) : "f"(lo), "f"(hi)); return r;
}
__device__ __forceinline__ ull fma2(ull a, ull b, ull c) {
    ull d; asm("fma.rn.f32x2 %0, %1, %2, %3;" : "=l"(d) : "l"(a), "l"(b), "l"(c)); return d;
}
__device__ __forceinline__ float2 upk2(ull v) {
    float2 f; asm("mov.b64 {%0,%1}, %2;" : "=f"(f.x), "=f"(f.y) : "l"(v)); return f;
}

// ---------------- conv1 (im2col GEMM, M=32256 K=2048 N=256) + BN1 ----------------
// 128 threads, block tile 128(M)x128(N)x16(K). 4 warps in 2(M)x2(N) -> warp 64x64.
// Lane grid 8(mq) x 4(nq), micro-tile 8Mx16N: per kk per warp only 6 LDS.128
// (3072B write-back) vs 64 fma2 -> fma-pipe bound, not LDS-bound.
__global__ __launch_bounds__(128, 2)
void conv1_gemm(const float* __restrict__ x,
                const float* __restrict__ c1w,
                const float* __restrict__ c1b,
                const float* __restrict__ bn1g,
                const float* __restrict__ bn1b,
                const float* __restrict__ bn1m,
                const float* __restrict__ bn1v)
{
    __shared__ __align__(16) float As[2][16][128];
    __shared__ __align__(16) float Bs[2][16][128];
    const int tid  = threadIdx.x;
    const int lane = tid & 31;
    const int w    = tid >> 5;
    const int mBase = blockIdx.x * 128;
    const int nBase = blockIdx.y * 128;

    const int warp_m = (w & 1) * 64;
    const int warp_n = (w >> 1) * 64;
    const int mq = (lane >> 2) * 8;      // 0..56
    const int nq = (lane & 3) * 16;      // 0..48

    // ---- A loader: thread tid loads 16 consecutive k for im2col row (mBase+tid)
    const int m_row = mBase + tid;
    const int n_idx = m_row / TT;
    const int t_idx = m_row - n_idx * TT;
    const float* xrow = x + ((size_t)n_idx * CIN) * LIN + t_idx * STR1;

    // ---- B loader: thread tid loads 16 consecutive k for co (nBase+tid)
    const float* wrow = c1w + (size_t)(nBase + tid) * KTOT;

    ull acc[8][8];
    #pragma unroll
    for (int i = 0; i < 8; i++)
        #pragma unroll
        for (int j = 0; j < 8; j++) acc[i][j] = 0ULL;

    float4 ap0, ap1, ap2, ap3, bq0, bq1, bq2, bq3;

    #define LOAD_REGS(KB) {                                                    \
        const float* abase = xrow + (size_t)((KB) >> 5) * LIN + ((KB) & 31);   \
        ap0 = *(const float4*)(abase);                                         \
        ap1 = *(const float4*)(abase + 4);                                     \
        ap2 = *(const float4*)(abase + 8);                                     \
        ap3 = *(const float4*)(abase + 12);                                    \
        bq0 = *(const float4*)(wrow + (KB));                                   \
        bq1 = *(const float4*)(wrow + (KB) + 4);                               \
        bq2 = *(const float4*)(wrow + (KB) + 8);                               \
        bq3 = *(const float4*)(wrow + (KB) + 12);                              \
    }
    #define STORE_SMEM(B) {                                                    \
        As[B][0][tid]  = ap0.x; As[B][1][tid]  = ap0.y;                        \
        As[B][2][tid]  = ap0.z; As[B][3][tid]  = ap0.w;                        \
        As[B][4][tid]  = ap1.x; As[B][5][tid]  = ap1.y;                        \
        As[B][6][tid]  = ap1.z; As[B][7][tid]  = ap1.w;                        \
        As[B][8][tid]  = ap2.x; As[B][9][tid]  = ap2.y;                        \
        As[B][10][tid] = ap2.z; As[B][11][tid] = ap2.w;                        \
        As[B][12][tid] = ap3.x; As[B][13][tid] = ap3.y;                        \
        As[B][14][tid] = ap3.z; As[B][15][tid] = ap3.w;                        \
        Bs[B][0][tid]  = bq0.x; Bs[B][1][tid]  = bq0.y;                        \
        Bs[B][2][tid]  = bq0.z; Bs[B][3][tid]  = bq0.w;                        \
        Bs[B][4][tid]  = bq1.x; Bs[B][5][tid]  = bq1.y;                        \
        Bs[B][6][tid]  = bq1.z; Bs[B][7][tid]  = bq1.w;                        \
        Bs[B][8][tid]  = bq2.x; Bs[B][9][tid]  = bq2.y;                        \
        Bs[B][10][tid] = bq2.z; Bs[B][11][tid] = bq2.w;                        \
        Bs[B][12][tid] = bq3.x; Bs[B][13][tid] = bq3.y;                        \
        Bs[B][14][tid] = bq3.z; Bs[B][15][tid] = bq3.w;                        \
    }

    LOAD_REGS(0);
    STORE_SMEM(0);
    __syncthreads();

    int buf = 0;
    for (int kb = 0; kb < KTOT; kb += 16) {
        const bool more = (kb + 16) < KTOT;
        if (more) LOAD_REGS(kb + 16);

        const float (*A)[128] = As[buf];
        const float (*B)[128] = Bs[buf];
        #pragma unroll
        for (int kk = 0; kk < 16; kk++) {
            float4 x0 = *(const float4*)&A[kk][warp_m + mq];
            float4 x1 = *(const float4*)&A[kk][warp_m + mq + 4];
            ulonglong2 q0 = *(const ulonglong2*)&B[kk][warp_n + nq];
            ulonglong2 q1 = *(const ulonglong2*)&B[kk][warp_n + nq + 4];
            ulonglong2 q2 = *(const ulonglong2*)&B[kk][warp_n + nq + 8];
            ulonglong2 q3 = *(const ulonglong2*)&B[kk][warp_n + nq + 12];
            ull ap;
            #define FMA_ROW(I, AV)                        \
                ap = pk2(AV, AV);                         \
                acc[I][0] = fma2(ap, q0.x, acc[I][0]);    \
                acc[I][1] = fma2(ap, q0.y, acc[I][1]);    \
                acc[I][2] = fma2(ap, q1.x, acc[I][2]);    \
                acc[I][3] = fma2(ap, q1.y, acc[I][3]);    \
                acc[I][4] = fma2(ap, q2.x, acc[I][4]);    \
                acc[I][5] = fma2(ap, q2.y, acc[I][5]);    \
                acc[I][6] = fma2(ap, q3.x, acc[I][6]);    \
                acc[I][7] = fma2(ap, q3.y, acc[I][7]);
            FMA_ROW(0, x0.x) FMA_ROW(1, x0.y) FMA_ROW(2, x0.z) FMA_ROW(3, x0.w)
            FMA_ROW(4, x1.x) FMA_ROW(5, x1.y) FMA_ROW(6, x1.z) FMA_ROW(7, x1.w)
            #undef FMA_ROW
        }
        if (more) STORE_SMEM(buf ^ 1);
        __syncthreads();
        buf ^= 1;
    }
    #undef LOAD_REGS
    #undef STORE_SMEM

    // epilogue: ((conv + b) - m) * (g/sqrt(v+eps)) + beta  -> g_z1 [n][t][co]
    float sc[16], bb[16], mm[16], cb[16];
    #pragma unroll
    for (int jj = 0; jj < 16; jj++) {
        int co = nBase + warp_n + nq + jj;
        sc[jj] = bn1g[co] / sqrtf(bn1v[co] + 1e-5f);
        bb[jj] = bn1b[co]; mm[jj] = bn1m[co]; cb[jj] = c1b[co];
    }
    #pragma unroll
    for (int i = 0; i < 8; i++) {
        int m = mBase + warp_m + mq + i;
        float o_[16];
        #pragma unroll
        for (int j = 0; j < 8; j++) {
            float2 v = upk2(acc[i][j]);
            o_[2 * j] = v.x; o_[2 * j + 1] = v.y;
        }
        #pragma unroll
        for (int jj = 0; jj < 16; jj++) {
            float t1 = (o_[jj] + cb[jj]) - mm[jj];
            o_[jj] = fmaf(t1, sc[jj], bb[jj]);
        }
        float* dst = g_z1 + (size_t)m * COUTC + nBase + warp_n + nq;
        *(float4*)(dst)      = make_float4(o_[0],  o_[1],  o_[2],  o_[3]);
        *(float4*)(dst + 4)  = make_float4(o_[4],  o_[5],  o_[6],  o_[7]);
        *(float4*)(dst + 8)  = make_float4(o_[8],  o_[9],  o_[10], o_[11]);
        *(float4*)(dst + 12) = make_float4(o_[12], o_[13], o_[14], o_[15]);
    }
}

// ---------------- prep: conv2/dense1 weight layouts + BN2 scale ----------------
__global__ void prep_kernel(const float* __restrict__ c2w,
                            const float* __restrict__ d1w,
                            const float* __restrict__ bn2g, const float* __restrict__ bn2v)
{
    int i = blockIdx.x * blockDim.x + threadIdx.x;
    if (i < COUTC * 3 * COUTC) {                  // conv2 w: pair-interleaved
        int row = i >> 8, j = i & 255;
        int ci = row / 3, k = row - 3 * ci;
        int co = (j >> 1) + 128 * (j & 1);
        g_c2wt[i] = c2w[(co * COUTC + ci) * 3 + k];
    }
    if (i < COUTC * COUTC) {                      // dense w1: [o][c] -> [c][o]
        int c = i >> 8, o = i & 255;
        g_d1wt[i] = d1w[o * COUTC + c];
    }
    if (i < COUTC) {
        g_bn2a[i] = bn2g[i] / sqrtf(bn2v[i] + 1e-5f);
    }
}

// ---------------- mega kernel ----------------
__global__ __launch_bounds__(512, 1)
void mega_kernel(const float* __restrict__ c2b,
                 const float* __restrict__ bn2b,
                 const float* __restrict__ bn2m,
                 const float* __restrict__ d2w,
                 float* __restrict__ out)
{
    extern __shared__ float sm[];
    float* zin  = sm;                          // dup-z: [row 0..65][512] ; later reused [o][BSTR]
    float* bufA = sm + ZROWS * 2 * COUTC;      // [co][BSTR]

    const int n = blockIdx.x;
    const int tid = threadIdx.x;

    // ---- load z1[n] into dup rows 1..63; zero rows 0,64,65 ----
    {
        float4* z4 = (float4*)zin;                                  // row 0: 512 floats
        for (int i = tid; i < (2 * COUTC) / 4; i += 512) z4[i] = make_float4(0, 0, 0, 0);
        float4* zp4 = (float4*)(zin + 64 * 2 * COUTC);              // rows 64,65: 1024 floats
        for (int i = tid; i < (4 * COUTC) / 4; i += 512) zp4[i] = make_float4(0, 0, 0, 0);
        const float4* src = (const float4*)(g_z1 + (size_t)n * (TT * COUTC));
        float4* dstv = (float4*)(zin + 2 * COUTC);                  // row 1 start
        for (int i = tid; i < (TT * COUTC) / 4; i += 512) {
            float4 v = src[i];
            dstv[2 * i]     = make_float4(v.x, v.x, v.y, v.y);
            dstv[2 * i + 1] = make_float4(v.z, v.z, v.w, v.w);
        }
    }
    __syncthreads();

    // ---- conv2 (k=3,p=1) + BN2 : fp32x2 lanes = (co, co+128), prefetched weights ----
    {
        const int cog = tid & 127;
        const int th  = tid >> 7;
        const int t0  = th * 16;
        ull acc[16];
        #pragma unroll
        for (int t = 0; t < 16; t++) acc[t] = 0ULL;

        const float* zb = zin + t0 * (2 * COUTC);     // row t0 => t = t0-1
        const ull* wb = (const ull*)g_c2wt;

        ull w0 = wb[cog], w1 = wb[128 + cog], w2 = wb[256 + cog];
        #pragma unroll 2
        for (int ci = 0; ci < COUTC; ci++) {
            // prefetch next ci's weights (wrap at end; harmless reload)
            const int cin = (ci + 1) & 255;
            const ull* wn = wb + cin * 384;
            ull nw0 = wn[cog], nw1 = wn[128 + cog], nw2 = wn[256 + cog];

            ull zz[18];
            #pragma unroll
            for (int j = 0; j < 18; j++)
                zz[j] = *(const ull*)(zb + j * (2 * COUTC) + 2 * ci);
            #pragma unroll
            for (int t = 0; t < 16; t++) {
                acc[t] = fma2(w0, zz[t],     acc[t]);
                acc[t] = fma2(w1, zz[t + 1], acc[t]);
                acc[t] = fma2(w2, zz[t + 2], acc[t]);
            }
            w0 = nw0; w1 = nw1; w2 = nw2;
        }
        const int coA = cog, coB = cog + 128;
        const float cbA = c2b[coA], mA = bn2m[coA], sA = g_bn2a[coA], bA = bn2b[coA];
        const float cbB = c2b[coB], mB = bn2m[coB], sB = g_bn2a[coB], bB = bn2b[coB];
        #pragma unroll
        for (int t = 0; t < 16; t++) {
            float2 v = upk2(acc[t]);
            int tt = t0 + t;
            bufA[coA * BSTR + tt] = fmaf((v.x + cbA) - mA, sA, bA);
            bufA[coB * BSTR + tt] = fmaf((v.y + cbB) - mB, sB, bB);
        }
    }
    __syncthreads();

    // ---- encoder CUBA LIF: thr 0.3, cd 0.9, vd 0.9 ----
    if (tid < COUTC) {
        float* row = bufA + tid * BSTR;
        const float cd = (float)(1.0 - 0.9);
        const float vd = (float)(1.0 - 0.9);
        float cur = 0.0f, vol = 0.0f;
        #pragma unroll 1
        for (int t = 0; t < TT; t++) {
            float xv = row[t];
            cur = fmaf(cd, cur, xv);
            vol = fmaf(vd, vol, cur);
            float s = ((vol - 0.3f) >= 0.0f) ? 1.0f : 0.0f;
            row[t] = s;
            vol = vol * (1.0f - s);
        }
        row[TT] = 0.0f;
    }
    __syncthreads();

    // ---- dense1: fp32x2 lanes = t-pairs, prefetched weights ----
    {
        const int og = tid & 127;
        const int th = tid >> 7;
        const int t0 = th * 16;
        ull a0[8], a1[8];
        #pragma unroll
        for (int p = 0; p < 8; p++) { a0[p] = 0ULL; a1[p] = 0ULL; }

        float wa = g_d1wt[og], wbv = g_d1wt[og + 128];
        #pragma unroll 2
        for (int c = 0; c < COUTC; c++) {
            const int cn = (c + 1) & 255;
            float nwa = g_d1wt[cn * COUTC + og];
            float nwb = g_d1wt[cn * COUTC + og + 128];

            ull wap = pk2(wa, wa), wbp = pk2(wbv, wbv);
            const ull* sp = (const ull*)(bufA + c * BSTR + t0);
            #pragma unroll
            for (int p = 0; p < 8; p++) {
                ull s = sp[p];
                a0[p] = fma2(wap, s, a0[p]);
                a1[p] = fma2(wbp, s, a1[p]);
            }
            wa = nwa; wbv = nwb;
        }
        ull* d0 = (ull*)(zin + og * BSTR + t0);
        ull* d1 = (ull*)(zin + (og + 128) * BSTR + t0);
        #pragma unroll
        for (int p = 0; p < 8; p++) { d0[p] = a0[p]; d1[p] = a1[p]; }
    }
    __syncthreads();

    // ---- dense1 CUBA LIF: thr 0.1, cd=1, vd=0.1 ----
    if (tid < COUTC) {
        float* row = zin + tid * BSTR;
        const float vdD = (float)(1.0 - 0.1);
        float vol = 0.0f;
        #pragma unroll 1
        for (int t = 0; t < TT; t++) {
            float xv = row[t];
            vol = fmaf(vdD, vol, xv);
            float s = ((vol - 0.1f) >= 0.0f) ? 1.0f : 0.0f;
            row[t] = s;
            vol = vol * (1.0f - s);
        }
    }
    __syncthreads();

    // ---- dense2: [2 x 256] ----
    if (tid < NCLS * TT) {
        int cls = tid / TT, t = tid - cls * TT;
        const float* w = d2w + cls * COUTC;
        float a = 0.0f;
        #pragma unroll 4
        for (int c = 0; c < COUTC; c++) a = fmaf(w[c], zin[c * BSTR + t], a);
        bufA[tid] = a;
    }
    __syncthreads();

    // ---- dense2 CUBA LIF + output ----
    if (tid < NCLS) {
        const float vdD = (float)(1.0 - 0.1);
        float vol = 0.0f;
        const float* rowi = bufA + tid * TT;
        float* rowo = out + (size_t)n * (NCLS * TT) + tid * TT;
        #pragma unroll 1
        for (int t = 0; t < TT; t++) {
            float xv = rowi[t];
            vol = fmaf(vdD, vol, xv);
            float s = ((vol - 0.1f) >= 0.0f) ? 1.0f : 0.0f;
            rowo[t] = s;
            vol = vol * (1.0f - s);
        }
    }
}

// ---------------- launch ----------------
extern "C" void kernel_launch(void* const* d_in, const int* in_sizes, int n_in,
                              void* d_out, int out_size)
{
    const float* x    = (const float*)d_in[0];
    const float* c1w  = (const float*)d_in[1];
    const float* c1b  = (const float*)d_in[2];
    const float* bn1g = (const float*)d_in[3];
    const float* bn1b = (const float*)d_in[4];
    const float* bn1m = (const float*)d_in[5];
    const float* bn1v = (const float*)d_in[6];
    const float* c2w  = (const float*)d_in[7];
    const float* c2b  = (const float*)d_in[8];
    const float* bn2g = (const float*)d_in[9];
    const float* bn2b = (const float*)d_in[10];
    const float* bn2m = (const float*)d_in[11];
    const float* bn2v = (const float*)d_in[12];
    const float* d1w  = (const float*)d_in[13];
    const float* d2w  = (const float*)d_in[14];
    float* out = (float*)d_out;

    const int smem_bytes = (ZROWS * 2 * COUTC + COUTC * BSTR) * (int)sizeof(float);
    cudaFuncSetAttribute(mega_kernel, cudaFuncAttributeMaxDynamicSharedMemorySize, smem_bytes);

    // conv1 first (self-contained) so the profiler's first-node capture shows it
    dim3 g1(252, 2);
    conv1_gemm<<<g1, 128>>>(x, c1w, c1b, bn1g, bn1b, bn1m, bn1v);

    prep_kernel<<<768, 256>>>(c2w, d1w, bn2g, bn2v);

    mega_kernel<<<BATCH, 512, smem_bytes>>>(c2b, bn2b, bn2m, d2w, out);
}

// round 8
// speedup vs baseline: 1.3501x; 1.0643x over previous
#include <cuda_runtime.h>
#include <math.h>

typedef unsigned long long ull;

#define BATCH 512
#define CIN   64
#define LIN   1024
#define COUTC 256
#define K1    32
#define STR1  16
#define TT    63
#define NCLS  2
#define KTOT  2048   // CIN*K1

#define ZROWS 66     // dup-z rows: t = -1 .. 64  (row = t+1), each row 512 floats (dup)
#define BSTR  66     // bufA / d1 row stride

// ---------------- device scratch ----------------
__device__ float g_z1[BATCH * TT * COUTC];       // [n][t][co]
__device__ float g_c2wt[COUTC * 3 * COUTC];      // [(ci*3+k)][2*cog+half]  (co pairs interleaved)
__device__ float g_d1wt[COUTC * COUTC];          // [c][o]
__device__ float g_bn2a[COUTC];

// ---------------- packed fp32x2 helpers ----------------
__device__ __forceinline__ ull pk2(float lo, float hi) {
    ull r; asm("mov.b64 %0, {%1,%2};" : "=l"(r) : "f"(lo), "f"(hi)); return r;
}
__device__ __forceinline__ ull fma2(ull a, ull b, ull c) {
    ull d; asm("fma.rn.f32x2 %0, %1, %2, %3;" : "=l"(d) : "l"(a), "l"(b), "l"(c)); return d;
}
__device__ __forceinline__ float2 upk2(ull v) {
    float2 f; asm("mov.b64 {%0,%1}, %2;" : "=f"(f.x), "=f"(f.y) : "l"(v)); return f;
}

// ---------------- conv1 (im2col GEMM, M=32256 K=2048 N=256) + BN1 ----------------
// 256 threads, block 128(M)x128(N)x16(K) double-buffered. 8 warps in 4(M)x2(N),
// warp tile 32x64, lane grid 4(g,m)x8(j,n), micro-tile 8x8 in 4-float chunks:
//   m rows  = warp_m + {4g..4g+3} u {16+4g..19+4g}
//   n cols  = warp_n + {4j..4j+3} u {32+4j..35+4j}
// -> every LDS.128 covers contiguous smem: A loads 64B-contig (banks 0-15/16-31),
//    B loads 128B-contig full wavefronts. ZERO bank conflicts in the hot loop.
__global__ __launch_bounds__(256, 2)
void conv1_gemm(const float* __restrict__ x,
                const float* __restrict__ c1w,
                const float* __restrict__ c1b,
                const float* __restrict__ bn1g,
                const float* __restrict__ bn1b,
                const float* __restrict__ bn1m,
                const float* __restrict__ bn1v)
{
    __shared__ __align__(16) float As[2][16][128];
    __shared__ __align__(16) float Bs[2][16][128];
    const int tid  = threadIdx.x;
    const int lane = tid & 31;
    const int w    = tid >> 5;
    const int mBase = blockIdx.x * 128;
    const int nBase = blockIdx.y * 128;

    const int warp_m = (w & 3) * 32;
    const int warp_n = (w >> 2) * 64;
    const int g = lane >> 3;            // 0..3  m-chunk group
    const int j = lane & 7;             // 0..7  n-chunk group

    // ---- loaders: am = tid&127 (row), kq = (tid>>7)*8 (k-half) ----
    const int am = tid & 127;
    const int kq = (tid >> 7) * 8;
    const int m_row = mBase + am;
    const int n_idx = m_row / TT;
    const int t_idx = m_row - n_idx * TT;
    const float* xrow = x + ((size_t)n_idx * CIN) * LIN + t_idx * STR1;
    const float* wrow = c1w + (size_t)(nBase + am) * KTOT;

    ull acc[8][4];
    #pragma unroll
    for (int i = 0; i < 8; i++)
        #pragma unroll
        for (int q = 0; q < 4; q++) acc[i][q] = 0ULL;

    float4 ap0, ap1, bp0, bp1;

    #define LOAD_REGS(KB) {                                                    \
        int col = (KB) + kq;                                                   \
        const float* abase = xrow + (size_t)(col >> 5) * LIN + (col & 31);     \
        ap0 = *(const float4*)(abase);                                         \
        ap1 = *(const float4*)(abase + 4);                                     \
        bp0 = *(const float4*)(wrow + col);                                    \
        bp1 = *(const float4*)(wrow + col + 4);                                \
    }
    #define STORE_SMEM(B) {                                                    \
        As[B][kq + 0][am] = ap0.x; As[B][kq + 1][am] = ap0.y;                  \
        As[B][kq + 2][am] = ap0.z; As[B][kq + 3][am] = ap0.w;                  \
        As[B][kq + 4][am] = ap1.x; As[B][kq + 5][am] = ap1.y;                  \
        As[B][kq + 6][am] = ap1.z; As[B][kq + 7][am] = ap1.w;                  \
        Bs[B][kq + 0][am] = bp0.x; Bs[B][kq + 1][am] = bp0.y;                  \
        Bs[B][kq + 2][am] = bp0.z; Bs[B][kq + 3][am] = bp0.w;                  \
        Bs[B][kq + 4][am] = bp1.x; Bs[B][kq + 5][am] = bp1.y;                  \
        Bs[B][kq + 6][am] = bp1.z; Bs[B][kq + 7][am] = bp1.w;                  \
    }

    LOAD_REGS(0);
    STORE_SMEM(0);
    __syncthreads();

    int buf = 0;
    for (int kb = 0; kb < KTOT; kb += 16) {
        const bool more = (kb + 16) < KTOT;
        if (more) LOAD_REGS(kb + 16);

        const float (*A)[128] = As[buf];
        const float (*B)[128] = Bs[buf];
        #pragma unroll
        for (int kk = 0; kk < 16; kk++) {
            float4 x0 = *(const float4*)&A[kk][warp_m + 4 * g];           // m 4g..4g+3
            float4 x1 = *(const float4*)&A[kk][warp_m + 16 + 4 * g];      // m 16+4g..
            ulonglong2 n0 = *(const ulonglong2*)&B[kk][warp_n + 4 * j];   // n 4j..4j+3
            ulonglong2 n1 = *(const ulonglong2*)&B[kk][warp_n + 32 + 4 * j];
            ull ap;
            #define FMA_ROW(I, AV)                        \
                ap = pk2(AV, AV);                         \
                acc[I][0] = fma2(ap, n0.x, acc[I][0]);    \
                acc[I][1] = fma2(ap, n0.y, acc[I][1]);    \
                acc[I][2] = fma2(ap, n1.x, acc[I][2]);    \
                acc[I][3] = fma2(ap, n1.y, acc[I][3]);
            FMA_ROW(0, x0.x) FMA_ROW(1, x0.y) FMA_ROW(2, x0.z) FMA_ROW(3, x0.w)
            FMA_ROW(4, x1.x) FMA_ROW(5, x1.y) FMA_ROW(6, x1.z) FMA_ROW(7, x1.w)
            #undef FMA_ROW
        }
        if (more) STORE_SMEM(buf ^ 1);
        __syncthreads();
        buf ^= 1;
    }
    #undef LOAD_REGS
    #undef STORE_SMEM

    // epilogue: ((conv + b) - m) * (g/sqrt(v+eps)) + beta  -> g_z1 [n][t][co]
    // thread's 8 n columns: nBase + warp_n + {4j..4j+3, 32+4j..35+4j}
    float sc[8], bb[8], mm[8], cb[8];
    #pragma unroll
    for (int jj = 0; jj < 8; jj++) {
        int co = nBase + warp_n + ((jj < 4) ? (4 * j + jj) : (32 + 4 * j + jj - 4));
        sc[jj] = bn1g[co] / sqrtf(bn1v[co] + 1e-5f);
        bb[jj] = bn1b[co]; mm[jj] = bn1m[co]; cb[jj] = c1b[co];
    }
    #pragma unroll
    for (int i = 0; i < 8; i++) {
        int m = mBase + warp_m + ((i < 4) ? (4 * g + i) : (16 + 4 * g + i - 4));
        float o_[8];
        #pragma unroll
        for (int q = 0; q < 4; q++) {
            float2 v = upk2(acc[i][q]);
            o_[2 * q] = v.x; o_[2 * q + 1] = v.y;
        }
        #pragma unroll
        for (int jj = 0; jj < 8; jj++) {
            float t1 = (o_[jj] + cb[jj]) - mm[jj];
            o_[jj] = fmaf(t1, sc[jj], bb[jj]);
        }
        float* dst = g_z1 + (size_t)m * COUTC + nBase + warp_n;
        *(float4*)(dst + 4 * j)      = make_float4(o_[0], o_[1], o_[2], o_[3]);
        *(float4*)(dst + 32 + 4 * j) = make_float4(o_[4], o_[5], o_[6], o_[7]);
    }
}

// ---------------- prep: conv2/dense1 weight layouts + BN2 scale ----------------
__global__ void prep_kernel(const float* __restrict__ c2w,
                            const float* __restrict__ d1w,
                            const float* __restrict__ bn2g, const float* __restrict__ bn2v)
{
    int i = blockIdx.x * blockDim.x + threadIdx.x;
    if (i < COUTC * 3 * COUTC) {                  // conv2 w: pair-interleaved
        int row = i >> 8, jj = i & 255;
        int ci = row / 3, k = row - 3 * ci;
        int co = (jj >> 1) + 128 * (jj & 1);
        g_c2wt[i] = c2w[(co * COUTC + ci) * 3 + k];
    }
    if (i < COUTC * COUTC) {                      // dense w1: [o][c] -> [c][o]
        int c = i >> 8, o = i & 255;
        g_d1wt[i] = d1w[o * COUTC + c];
    }
    if (i < COUTC) {
        g_bn2a[i] = bn2g[i] / sqrtf(bn2v[i] + 1e-5f);
    }
}

// ---------------- mega kernel ----------------
__global__ __launch_bounds__(512, 1)
void mega_kernel(const float* __restrict__ c2b,
                 const float* __restrict__ bn2b,
                 const float* __restrict__ bn2m,
                 const float* __restrict__ d2w,
                 float* __restrict__ out)
{
    extern __shared__ float sm[];
    float* zin  = sm;                          // dup-z: [row 0..65][512] ; later reused [o][BSTR]
    float* bufA = sm + ZROWS * 2 * COUTC;      // [co][BSTR]

    const int n = blockIdx.x;
    const int tid = threadIdx.x;

    // ---- load z1[n] into dup rows 1..63; zero rows 0,64,65 ----
    {
        float4* z4 = (float4*)zin;                                  // row 0: 512 floats
        for (int i = tid; i < (2 * COUTC) / 4; i += 512) z4[i] = make_float4(0, 0, 0, 0);
        float4* zp4 = (float4*)(zin + 64 * 2 * COUTC);              // rows 64,65: 1024 floats
        for (int i = tid; i < (4 * COUTC) / 4; i += 512) zp4[i] = make_float4(0, 0, 0, 0);
        const float4* src = (const float4*)(g_z1 + (size_t)n * (TT * COUTC));
        float4* dstv = (float4*)(zin + 2 * COUTC);                  // row 1 start
        for (int i = tid; i < (TT * COUTC) / 4; i += 512) {
            float4 v = src[i];
            dstv[2 * i]     = make_float4(v.x, v.x, v.y, v.y);
            dstv[2 * i + 1] = make_float4(v.z, v.z, v.w, v.w);
        }
    }
    __syncthreads();

    // ---- conv2 (k=3,p=1) + BN2 : fp32x2 lanes = (co, co+128), prefetched weights ----
    {
        const int cog = tid & 127;
        const int th  = tid >> 7;
        const int t0  = th * 16;
        ull acc[16];
        #pragma unroll
        for (int t = 0; t < 16; t++) acc[t] = 0ULL;

        const float* zb = zin + t0 * (2 * COUTC);     // row t0 => t = t0-1
        const ull* wb = (const ull*)g_c2wt;

        ull w0 = wb[cog], w1 = wb[128 + cog], w2 = wb[256 + cog];
        #pragma unroll 2
        for (int ci = 0; ci < COUTC; ci++) {
            // prefetch next ci's weights (wrap at end; harmless reload)
            const int cin = (ci + 1) & 255;
            const ull* wn = wb + cin * 384;
            ull nw0 = wn[cog], nw1 = wn[128 + cog], nw2 = wn[256 + cog];

            ull zz[18];
            #pragma unroll
            for (int jj = 0; jj < 18; jj++)
                zz[jj] = *(const ull*)(zb + jj * (2 * COUTC) + 2 * ci);
            #pragma unroll
            for (int t = 0; t < 16; t++) {
                acc[t] = fma2(w0, zz[t],     acc[t]);
                acc[t] = fma2(w1, zz[t + 1], acc[t]);
                acc[t] = fma2(w2, zz[t + 2], acc[t]);
            }
            w0 = nw0; w1 = nw1; w2 = nw2;
        }
        const int coA = cog, coB = cog + 128;
        const float cbA = c2b[coA], mA = bn2m[coA], sA = g_bn2a[coA], bA = bn2b[coA];
        const float cbB = c2b[coB], mB = bn2m[coB], sB = g_bn2a[coB], bB = bn2b[coB];
        #pragma unroll
        for (int t = 0; t < 16; t++) {
            float2 v = upk2(acc[t]);
            int tt = t0 + t;
            bufA[coA * BSTR + tt] = fmaf((v.x + cbA) - mA, sA, bA);
            bufA[coB * BSTR + tt] = fmaf((v.y + cbB) - mB, sB, bB);
        }
    }
    __syncthreads();

    // ---- encoder CUBA LIF: thr 0.3, cd 0.9, vd 0.9 ----
    if (tid < COUTC) {
        float* row = bufA + tid * BSTR;
        const float cd = (float)(1.0 - 0.9);
        const float vd = (float)(1.0 - 0.9);
        float cur = 0.0f, vol = 0.0f;
        #pragma unroll 1
        for (int t = 0; t < TT; t++) {
            float xv = row[t];
            cur = fmaf(cd, cur, xv);
            vol = fmaf(vd, vol, cur);
            float s = ((vol - 0.3f) >= 0.0f) ? 1.0f : 0.0f;
            row[t] = s;
            vol = vol * (1.0f - s);
        }
        row[TT] = 0.0f;
    }
    __syncthreads();

    // ---- dense1: fp32x2 lanes = t-pairs, prefetched weights ----
    {
        const int og = tid & 127;
        const int th = tid >> 7;
        const int t0 = th * 16;
        ull a0[8], a1[8];
        #pragma unroll
        for (int p = 0; p < 8; p++) { a0[p] = 0ULL; a1[p] = 0ULL; }

        float wa = g_d1wt[og], wbv = g_d1wt[og + 128];
        #pragma unroll 2
        for (int c = 0; c < COUTC; c++) {
            const int cn = (c + 1) & 255;
            float nwa = g_d1wt[cn * COUTC + og];
            float nwb = g_d1wt[cn * COUTC + og + 128];

            ull wap = pk2(wa, wa), wbp = pk2(wbv, wbv);
            const ull* sp = (const ull*)(bufA + c * BSTR + t0);
            #pragma unroll
            for (int p = 0; p < 8; p++) {
                ull s = sp[p];
                a0[p] = fma2(wap, s, a0[p]);
                a1[p] = fma2(wbp, s, a1[p]);
            }
            wa = nwa; wbv = nwb;
        }
        ull* d0 = (ull*)(zin + og * BSTR + t0);
        ull* d1 = (ull*)(zin + (og + 128) * BSTR + t0);
        #pragma unroll
        for (int p = 0; p < 8; p++) { d0[p] = a0[p]; d1[p] = a1[p]; }
    }
    __syncthreads();

    // ---- dense1 CUBA LIF: thr 0.1, cd=1, vd=0.1 ----
    if (tid < COUTC) {
        float* row = zin + tid * BSTR;
        const float vdD = (float)(1.0 - 0.1);
        float vol = 0.0f;
        #pragma unroll 1
        for (int t = 0; t < TT; t++) {
            float xv = row[t];
            vol = fmaf(vdD, vol, xv);
            float s = ((vol - 0.1f) >= 0.0f) ? 1.0f : 0.0f;
            row[t] = s;
            vol = vol * (1.0f - s);
        }
    }
    __syncthreads();

    // ---- dense2: [2 x 256] ----
    if (tid < NCLS * TT) {
        int cls = tid / TT, t = tid - cls * TT;
        const float* w = d2w + cls * COUTC;
        float a = 0.0f;
        #pragma unroll 4
        for (int c = 0; c < COUTC; c++) a = fmaf(w[c], zin[c * BSTR + t], a);
        bufA[tid] = a;
    }
    __syncthreads();

    // ---- dense2 CUBA LIF + output ----
    if (tid < NCLS) {
        const float vdD = (float)(1.0 - 0.1);
        float vol = 0.0f;
        const float* rowi = bufA + tid * TT;
        float* rowo = out + (size_t)n * (NCLS * TT) + tid * TT;
        #pragma unroll 1
        for (int t = 0; t < TT; t++) {
            float xv = rowi[t];
            vol = fmaf(vdD, vol, xv);
            float s = ((vol - 0.1f) >= 0.0f) ? 1.0f : 0.0f;
            rowo[t] = s;
            vol = vol * (1.0f - s);
        }
    }
}

// ---------------- launch ----------------
extern "C" void kernel_launch(void* const* d_in, const int* in_sizes, int n_in,
                              void* d_out, int out_size)
{
    const float* x    = (const float*)d_in[0];
    const float* c1w  = (const float*)d_in[1];
    const float* c1b  = (const float*)d_in[2];
    const float* bn1g = (const float*)d_in[3];
    const float* bn1b = (const float*)d_in[4];
    const float* bn1m = (const float*)d_in[5];
    const float* bn1v = (const float*)d_in[6];
    const float* c2w  = (const float*)d_in[7];
    const float* c2b  = (const float*)d_in[8];
    const float* bn2g = (const float*)d_in[9];
    const float* bn2b = (const float*)d_in[10];
    const float* bn2m = (const float*)d_in[11];
    const float* bn2v = (const float*)d_in[12];
    const float* d1w  = (const float*)d_in[13];
    const float* d2w  = (const float*)d_in[14];
    float* out = (float*)d_out;

    const int smem_bytes = (ZROWS * 2 * COUTC + COUTC * BSTR) * (int)sizeof(float);
    cudaFuncSetAttribute(mega_kernel, cudaFuncAttributeMaxDynamicSharedMemorySize, smem_bytes);

    // conv1 first (self-contained) so the profiler's first-node capture shows it
    dim3 g1(252, 2);
    conv1_gemm<<<g1, 256>>>(x, c1w, c1b, bn1g, bn1b, bn1m, bn1v);

    prep_kernel<<<768, 256>>>(c2w, d1w, bn2g, bn2v);

    mega_kernel<<<BATCH, 512, smem_bytes>>>(c2b, bn2b, bn2m, d2w, out);
}

// round 9
// speedup vs baseline: 1.3702x; 1.0149x over previous
#include <cuda_runtime.h>
#include <math.h>

typedef unsigned long long ull;

#define BATCH 512
#define CIN   64
#define LIN   1024
#define COUTC 256
#define K1    32
#define STR1  16
#define TT    63
#define NCLS  2
#define KTOT  2048   // CIN*K1

#define ZROWS 66     // dup-z rows: t = -1 .. 64  (row = t+1), each row 512 floats (dup)
#define BSTR  66     // bufA / d1 row stride

// ---------------- device scratch ----------------
__device__ float g_z1[BATCH * TT * COUTC];       // [n][t][co]
__device__ float g_c2wt[COUTC * 3 * COUTC];      // [(ci*3+k)][2*cog+half]  (co pairs interleaved)
__device__ float g_d1wt[COUTC * COUTC];          // [c][o]
__device__ float g_bn2a[COUTC];

// ---------------- packed fp32x2 helpers ----------------
__device__ __forceinline__ ull pk2(float lo, float hi) {
    ull r; asm("mov.b64 %0, {%1,%2};" : "=l"(r) : "f"(lo), "f"(hi)); return r;
}
__device__ __forceinline__ ull fma2(ull a, ull b, ull c) {
    ull d; asm("fma.rn.f32x2 %0, %1, %2, %3;" : "=l"(d) : "l"(a), "l"(b), "l"(c)); return d;
}
__device__ __forceinline__ float2 upk2(ull v) {
    float2 f; asm("mov.b64 {%0,%1}, %2;" : "=f"(f.x), "=f"(f.y) : "l"(v)); return f;
}

// ---------------- conv1 (im2col GEMM, M=32256 K=2048 N=256) + BN1 ----------------
// 128 threads, block 128(M)x128(N)x16(K) double-buffered. 4 warps M-stacked,
// warp tile 32(M)x128(N). Lane grid 4(g,m)x8(j,n), micro-tile 8Mx16N in 4-float
// chunks:  m rows = w*32 + {4g..4g+3} u {16+4g..}
//          n cols = {4j.., 32+4j.., 64+4j.., 96+4j..}
// Per kk per warp: 6 conflict-free LDS.128 (A 64B-contig, B full 128B wavefronts)
// against 64 fma2 -> fma-pipe is the binding resource (~75% ceiling).
__global__ __launch_bounds__(128, 2)
void conv1_gemm(const float* __restrict__ x,
                const float* __restrict__ c1w,
                const float* __restrict__ c1b,
                const float* __restrict__ bn1g,
                const float* __restrict__ bn1b,
                const float* __restrict__ bn1m,
                const float* __restrict__ bn1v)
{
    __shared__ __align__(16) float As[2][16][128];
    __shared__ __align__(16) float Bs[2][16][128];
    const int tid  = threadIdx.x;
    const int lane = tid & 31;
    const int w    = tid >> 5;          // 0..3 -> m stripe
    const int mBase = blockIdx.x * 128;
    const int nBase = blockIdx.y * 128;

    const int warp_m = w * 32;
    const int g = lane >> 3;            // 0..3  m-chunk group
    const int j = lane & 7;             // 0..7  n-chunk group

    // ---- loaders: thread tid covers row tid (A: im2col row, B: co), 16 k each ----
    const int m_row = mBase + tid;
    const int n_idx = m_row / TT;
    const int t_idx = m_row - n_idx * TT;
    const float* xrow = x + ((size_t)n_idx * CIN) * LIN + t_idx * STR1;
    const float* wrow = c1w + (size_t)(nBase + tid) * KTOT;

    ull acc[8][8];
    #pragma unroll
    for (int i = 0; i < 8; i++)
        #pragma unroll
        for (int q = 0; q < 8; q++) acc[i][q] = 0ULL;

    float4 ap0, ap1, ap2, ap3, bq0, bq1, bq2, bq3;

    #define LOAD_REGS(KB) {                                                    \
        const float* abase = xrow + (size_t)((KB) >> 5) * LIN + ((KB) & 31);   \
        ap0 = *(const float4*)(abase);                                         \
        ap1 = *(const float4*)(abase + 4);                                     \
        ap2 = *(const float4*)(abase + 8);                                     \
        ap3 = *(const float4*)(abase + 12);                                    \
        bq0 = *(const float4*)(wrow + (KB));                                   \
        bq1 = *(const float4*)(wrow + (KB) + 4);                               \
        bq2 = *(const float4*)(wrow + (KB) + 8);                               \
        bq3 = *(const float4*)(wrow + (KB) + 12);                              \
    }
    #define STORE_SMEM(B) {                                                    \
        As[B][0][tid]  = ap0.x; As[B][1][tid]  = ap0.y;                        \
        As[B][2][tid]  = ap0.z; As[B][3][tid]  = ap0.w;                        \
        As[B][4][tid]  = ap1.x; As[B][5][tid]  = ap1.y;                        \
        As[B][6][tid]  = ap1.z; As[B][7][tid]  = ap1.w;                        \
        As[B][8][tid]  = ap2.x; As[B][9][tid]  = ap2.y;                        \
        As[B][10][tid] = ap2.z; As[B][11][tid] = ap2.w;                        \
        As[B][12][tid] = ap3.x; As[B][13][tid] = ap3.y;                        \
        As[B][14][tid] = ap3.z; As[B][15][tid] = ap3.w;                        \
        Bs[B][0][tid]  = bq0.x; Bs[B][1][tid]  = bq0.y;                        \
        Bs[B][2][tid]  = bq0.z; Bs[B][3][tid]  = bq0.w;                        \
        Bs[B][4][tid]  = bq1.x; Bs[B][5][tid]  = bq1.y;                        \
        Bs[B][6][tid]  = bq1.z; Bs[B][7][tid]  = bq1.w;                        \
        Bs[B][8][tid]  = bq2.x; Bs[B][9][tid]  = bq2.y;                        \
        Bs[B][10][tid] = bq2.z; Bs[B][11][tid] = bq2.w;                        \
        Bs[B][12][tid] = bq3.x; Bs[B][13][tid] = bq3.y;                        \
        Bs[B][14][tid] = bq3.z; Bs[B][15][tid] = bq3.w;                        \
    }

    LOAD_REGS(0);
    STORE_SMEM(0);
    __syncthreads();

    int buf = 0;
    for (int kb = 0; kb < KTOT; kb += 16) {
        const bool more = (kb + 16) < KTOT;
        if (more) LOAD_REGS(kb + 16);

        const float (*A)[128] = As[buf];
        const float (*B)[128] = Bs[buf];
        #pragma unroll
        for (int kk = 0; kk < 16; kk++) {
            float4 x0 = *(const float4*)&A[kk][warp_m + 4 * g];        // m 4g..4g+3
            float4 x1 = *(const float4*)&A[kk][warp_m + 16 + 4 * g];   // m 16+4g..
            ulonglong2 n0 = *(const ulonglong2*)&B[kk][4 * j];         // n 4j..4j+3
            ulonglong2 n1 = *(const ulonglong2*)&B[kk][32 + 4 * j];
            ulonglong2 n2 = *(const ulonglong2*)&B[kk][64 + 4 * j];
            ulonglong2 n3 = *(const ulonglong2*)&B[kk][96 + 4 * j];
            ull ap;
            #define FMA_ROW(I, AV)                        \
                ap = pk2(AV, AV);                         \
                acc[I][0] = fma2(ap, n0.x, acc[I][0]);    \
                acc[I][1] = fma2(ap, n0.y, acc[I][1]);    \
                acc[I][2] = fma2(ap, n1.x, acc[I][2]);    \
                acc[I][3] = fma2(ap, n1.y, acc[I][3]);    \
                acc[I][4] = fma2(ap, n2.x, acc[I][4]);    \
                acc[I][5] = fma2(ap, n2.y, acc[I][5]);    \
                acc[I][6] = fma2(ap, n3.x, acc[I][6]);    \
                acc[I][7] = fma2(ap, n3.y, acc[I][7]);
            FMA_ROW(0, x0.x) FMA_ROW(1, x0.y) FMA_ROW(2, x0.z) FMA_ROW(3, x0.w)
            FMA_ROW(4, x1.x) FMA_ROW(5, x1.y) FMA_ROW(6, x1.z) FMA_ROW(7, x1.w)
            #undef FMA_ROW
        }
        if (more) STORE_SMEM(buf ^ 1);
        __syncthreads();
        buf ^= 1;
    }
    #undef LOAD_REGS
    #undef STORE_SMEM

    // epilogue: ((conv + b) - m) * (g/sqrt(v+eps)) + beta  -> g_z1 [n][t][co]
    // thread's 16 n cols: nBase + {4j..4j+3, 32+4j.., 64+4j.., 96+4j..}
    float sc[16], bb[16], mm[16], cb[16];
    #pragma unroll
    for (int jj = 0; jj < 16; jj++) {
        int co = nBase + (jj >> 2) * 32 + 4 * j + (jj & 3);
        sc[jj] = bn1g[co] / sqrtf(bn1v[co] + 1e-5f);
        bb[jj] = bn1b[co]; mm[jj] = bn1m[co]; cb[jj] = c1b[co];
    }
    #pragma unroll
    for (int i = 0; i < 8; i++) {
        int m = mBase + warp_m + ((i < 4) ? (4 * g + i) : (16 + 4 * g + i - 4));
        float o_[16];
        #pragma unroll
        for (int q = 0; q < 8; q++) {
            float2 v = upk2(acc[i][q]);
            o_[2 * q] = v.x; o_[2 * q + 1] = v.y;
        }
        #pragma unroll
        for (int jj = 0; jj < 16; jj++) {
            float t1 = (o_[jj] + cb[jj]) - mm[jj];
            o_[jj] = fmaf(t1, sc[jj], bb[jj]);
        }
        float* dst = g_z1 + (size_t)m * COUTC + nBase;
        *(float4*)(dst + 4 * j)      = make_float4(o_[0],  o_[1],  o_[2],  o_[3]);
        *(float4*)(dst + 32 + 4 * j) = make_float4(o_[4],  o_[5],  o_[6],  o_[7]);
        *(float4*)(dst + 64 + 4 * j) = make_float4(o_[8],  o_[9],  o_[10], o_[11]);
        *(float4*)(dst + 96 + 4 * j) = make_float4(o_[12], o_[13], o_[14], o_[15]);
    }
}

// ---------------- prep: conv2/dense1 weight layouts + BN2 scale ----------------
__global__ void prep_kernel(const float* __restrict__ c2w,
                            const float* __restrict__ d1w,
                            const float* __restrict__ bn2g, const float* __restrict__ bn2v)
{
    int i = blockIdx.x * blockDim.x + threadIdx.x;
    if (i < COUTC * 3 * COUTC) {                  // conv2 w: pair-interleaved
        int row = i >> 8, jj = i & 255;
        int ci = row / 3, k = row - 3 * ci;
        int co = (jj >> 1) + 128 * (jj & 1);
        g_c2wt[i] = c2w[(co * COUTC + ci) * 3 + k];
    }
    if (i < COUTC * COUTC) {                      // dense w1: [o][c] -> [c][o]
        int c = i >> 8, o = i & 255;
        g_d1wt[i] = d1w[o * COUTC + c];
    }
    if (i < COUTC) {
        g_bn2a[i] = bn2g[i] / sqrtf(bn2v[i] + 1e-5f);
    }
}

// ---------------- mega kernel ----------------
__global__ __launch_bounds__(512, 1)
void mega_kernel(const float* __restrict__ c2b,
                 const float* __restrict__ bn2b,
                 const float* __restrict__ bn2m,
                 const float* __restrict__ d2w,
                 float* __restrict__ out)
{
    extern __shared__ float sm[];
    float* zin  = sm;                          // dup-z: [row 0..65][512] ; later reused [o][BSTR]
    float* bufA = sm + ZROWS * 2 * COUTC;      // [co][BSTR]

    const int n = blockIdx.x;
    const int tid = threadIdx.x;

    // ---- load z1[n] into dup rows 1..63; zero rows 0,64,65 ----
    {
        float4* z4 = (float4*)zin;                                  // row 0: 512 floats
        for (int i = tid; i < (2 * COUTC) / 4; i += 512) z4[i] = make_float4(0, 0, 0, 0);
        float4* zp4 = (float4*)(zin + 64 * 2 * COUTC);              // rows 64,65: 1024 floats
        for (int i = tid; i < (4 * COUTC) / 4; i += 512) zp4[i] = make_float4(0, 0, 0, 0);
        const float4* src = (const float4*)(g_z1 + (size_t)n * (TT * COUTC));
        float4* dstv = (float4*)(zin + 2 * COUTC);                  // row 1 start
        for (int i = tid; i < (TT * COUTC) / 4; i += 512) {
            float4 v = src[i];
            dstv[2 * i]     = make_float4(v.x, v.x, v.y, v.y);
            dstv[2 * i + 1] = make_float4(v.z, v.z, v.w, v.w);
        }
    }
    __syncthreads();

    // ---- conv2 (k=3,p=1) + BN2 : fp32x2 lanes = (co, co+128), prefetched weights ----
    {
        const int cog = tid & 127;
        const int th  = tid >> 7;
        const int t0  = th * 16;
        ull acc[16];
        #pragma unroll
        for (int t = 0; t < 16; t++) acc[t] = 0ULL;

        const float* zb = zin + t0 * (2 * COUTC);     // row t0 => t = t0-1
        const ull* wb = (const ull*)g_c2wt;

        ull w0 = wb[cog], w1 = wb[128 + cog], w2 = wb[256 + cog];
        #pragma unroll 2
        for (int ci = 0; ci < COUTC; ci++) {
            // prefetch next ci's weights (wrap at end; harmless reload)
            const int cin = (ci + 1) & 255;
            const ull* wn = wb + cin * 384;
            ull nw0 = wn[cog], nw1 = wn[128 + cog], nw2 = wn[256 + cog];

            ull zz[18];
            #pragma unroll
            for (int jj = 0; jj < 18; jj++)
                zz[jj] = *(const ull*)(zb + jj * (2 * COUTC) + 2 * ci);
            #pragma unroll
            for (int t = 0; t < 16; t++) {
                acc[t] = fma2(w0, zz[t],     acc[t]);
                acc[t] = fma2(w1, zz[t + 1], acc[t]);
                acc[t] = fma2(w2, zz[t + 2], acc[t]);
            }
            w0 = nw0; w1 = nw1; w2 = nw2;
        }
        const int coA = cog, coB = cog + 128;
        const float cbA = c2b[coA], mA = bn2m[coA], sA = g_bn2a[coA], bA = bn2b[coA];
        const float cbB = c2b[coB], mB = bn2m[coB], sB = g_bn2a[coB], bB = bn2b[coB];
        #pragma unroll
        for (int t = 0; t < 16; t++) {
            float2 v = upk2(acc[t]);
            int tt = t0 + t;
            bufA[coA * BSTR + tt] = fmaf((v.x + cbA) - mA, sA, bA);
            bufA[coB * BSTR + tt] = fmaf((v.y + cbB) - mB, sB, bB);
        }
    }
    __syncthreads();

    // ---- encoder CUBA LIF: thr 0.3, cd 0.9, vd 0.9 ----
    if (tid < COUTC) {
        float* row = bufA + tid * BSTR;
        const float cd = (float)(1.0 - 0.9);
        const float vd = (float)(1.0 - 0.9);
        float cur = 0.0f, vol = 0.0f;
        #pragma unroll 1
        for (int t = 0; t < TT; t++) {
            float xv = row[t];
            cur = fmaf(cd, cur, xv);
            vol = fmaf(vd, vol, cur);
            float s = ((vol - 0.3f) >= 0.0f) ? 1.0f : 0.0f;
            row[t] = s;
            vol = vol * (1.0f - s);
        }
        row[TT] = 0.0f;
    }
    __syncthreads();

    // ---- dense1: fp32x2 lanes = t-pairs, prefetched weights ----
    {
        const int og = tid & 127;
        const int th = tid >> 7;
        const int t0 = th * 16;
        ull a0[8], a1[8];
        #pragma unroll
        for (int p = 0; p < 8; p++) { a0[p] = 0ULL; a1[p] = 0ULL; }

        float wa = g_d1wt[og], wbv = g_d1wt[og + 128];
        #pragma unroll 2
        for (int c = 0; c < COUTC; c++) {
            const int cn = (c + 1) & 255;
            float nwa = g_d1wt[cn * COUTC + og];
            float nwb = g_d1wt[cn * COUTC + og + 128];

            ull wap = pk2(wa, wa), wbp = pk2(wbv, wbv);
            const ull* sp = (const ull*)(bufA + c * BSTR + t0);
            #pragma unroll
            for (int p = 0; p < 8; p++) {
                ull s = sp[p];
                a0[p] = fma2(wap, s, a0[p]);
                a1[p] = fma2(wbp, s, a1[p]);
            }
            wa = nwa; wbv = nwb;
        }
        ull* d0 = (ull*)(zin + og * BSTR + t0);
        ull* d1 = (ull*)(zin + (og + 128) * BSTR + t0);
        #pragma unroll
        for (int p = 0; p < 8; p++) { d0[p] = a0[p]; d1[p] = a1[p]; }
    }
    __syncthreads();

    // ---- dense1 CUBA LIF: thr 0.1, cd=1, vd=0.1 ----
    if (tid < COUTC) {
        float* row = zin + tid * BSTR;
        const float vdD = (float)(1.0 - 0.1);
        float vol = 0.0f;
        #pragma unroll 1
        for (int t = 0; t < TT; t++) {
            float xv = row[t];
            vol = fmaf(vdD, vol, xv);
            float s = ((vol - 0.1f) >= 0.0f) ? 1.0f : 0.0f;
            row[t] = s;
            vol = vol * (1.0f - s);
        }
    }
    __syncthreads();

    // ---- dense2: [2 x 256] ----
    if (tid < NCLS * TT) {
        int cls = tid / TT, t = tid - cls * TT;
        const float* w = d2w + cls * COUTC;
        float a = 0.0f;
        #pragma unroll 4
        for (int c = 0; c < COUTC; c++) a = fmaf(w[c], zin[c * BSTR + t], a);
        bufA[tid] = a;
    }
    __syncthreads();

    // ---- dense2 CUBA LIF + output ----
    if (tid < NCLS) {
        const float vdD = (float)(1.0 - 0.1);
        float vol = 0.0f;
        const float* rowi = bufA + tid * TT;
        float* rowo = out + (size_t)n * (NCLS * TT) + tid * TT;
        #pragma unroll 1
        for (int t = 0; t < TT; t++) {
            float xv = rowi[t];
            vol = fmaf(vdD, vol, xv);
            float s = ((vol - 0.1f) >= 0.0f) ? 1.0f : 0.0f;
            rowo[t] = s;
            vol = vol * (1.0f - s);
        }
    }
}

// ---------------- launch ----------------
extern "C" void kernel_launch(void* const* d_in, const int* in_sizes, int n_in,
                              void* d_out, int out_size)
{
    const float* x    = (const float*)d_in[0];
    const float* c1w  = (const float*)d_in[1];
    const float* c1b  = (const float*)d_in[2];
    const float* bn1g = (const float*)d_in[3];
    const float* bn1b = (const float*)d_in[4];
    const float* bn1m = (const float*)d_in[5];
    const float* bn1v = (const float*)d_in[6];
    const float* c2w  = (const float*)d_in[7];
    const float* c2b  = (const float*)d_in[8];
    const float* bn2g = (const float*)d_in[9];
    const float* bn2b = (const float*)d_in[10];
    const float* bn2m = (const float*)d_in[11];
    const float* bn2v = (const float*)d_in[12];
    const float* d1w  = (const float*)d_in[13];
    const float* d2w  = (const float*)d_in[14];
    float* out = (float*)d_out;

    const int smem_bytes = (ZROWS * 2 * COUTC + COUTC * BSTR) * (int)sizeof(float);
    cudaFuncSetAttribute(mega_kernel, cudaFuncAttributeMaxDynamicSharedMemorySize, smem_bytes);

    // conv1 first (self-contained) so the profiler's first-node capture shows it
    dim3 g1(252, 2);
    conv1_gemm<<<g1, 128>>>(x, c1w, c1b, bn1g, bn1b, bn1m, bn1v);

    prep_kernel<<<768, 256>>>(c2w, d1w, bn2g, bn2v);

    mega_kernel<<<BATCH, 512, smem_bytes>>>(c2b, bn2b, bn2m, d2w, out);
}